// round 1
// baseline (speedup 1.0000x reference)
#include <cuda_runtime.h>
#include <math.h>

// Problem constants
#define T_TOK 1024          // B*S tokens
#define DHID 1024           // hidden size D
#define NE 16               // routed experts
#define TOPK 8
#define NI 1024             // expert intermediate
#define ROUTE_SCALE 2.826f

// Dispatch rows: 8192 routed + 1024 shared, each expert segment padded to 64.
// Worst padding: 16*63 = 1008 -> 8192+1008+1024 = 10224 <= 10240.
#define ROWS_CAP 10240
#define ROW_TILES 160       // ROWS_CAP / 64

// ---------------- scratch (static __device__ arrays; no allocations) -------
__device__ float g_H[(size_t)ROWS_CAP * NI];     // SwiGLU intermediate
__device__ float g_Y[(size_t)ROWS_CAP * DHID];   // per-row expert output (pre-weighted)
__device__ int   g_row_token[ROWS_CAP];
__device__ float g_row_wt[ROWS_CAP];
__device__ int   g_tile_expert[ROW_TILES];
__device__ int   g_token_rows[T_TOK * 9];        // 8 routed rows + 1 shared row
__device__ int   g_counts[NE + 1];
__device__ int   g_fill[NE + 1];
__device__ int   g_offsets[NE + 2];
__device__ int   g_topk_idx[T_TOK * TOPK];
__device__ float g_topk_wt[T_TOK * TOPK];

// ---------------- K0: init ------------------------------------------------
__global__ void k_init() {
    int i = blockIdx.x * blockDim.x + threadIdx.x;
    if (i < ROWS_CAP) { g_row_token[i] = 0; g_row_wt[i] = 0.f; }
    if (i < ROW_TILES) g_tile_expert[i] = -1;
    if (i < NE + 1) { g_counts[i] = 0; g_fill[i] = 0; }
}

// ---------------- K1: routing (gates, sigmoid, top-8, norm, scale) --------
__global__ void __launch_bounds__(128) k_route(const float* __restrict__ x,
                                               const float* __restrict__ gw,
                                               const float* __restrict__ bias) {
    __shared__ float xs[DHID];
    __shared__ float gates[NE];
    int t = blockIdx.x, tid = threadIdx.x;
    for (int i = tid; i < DHID; i += 128) xs[i] = x[(size_t)t * DHID + i];
    __syncthreads();

    int e = tid >> 3, p = tid & 7;              // 8 threads per expert
    const float* w  = gw + e * DHID + p * 128;
    const float* xv = xs + p * 128;
    float s = 0.f;
#pragma unroll 8
    for (int d = 0; d < 128; d++) s += xv[d] * w[d];
    s += __shfl_down_sync(0xffffffffu, s, 4, 8);
    s += __shfl_down_sync(0xffffffffu, s, 2, 8);
    s += __shfl_down_sync(0xffffffffu, s, 1, 8);
    if (p == 0) gates[e] = s;
    __syncthreads();

    if (tid == 0) {
        float sc[NE], sel[NE];
        bool used[NE];
        for (int i = 0; i < NE; i++) {
            sc[i]  = 1.f / (1.f + expf(-gates[i]));   // sigmoid score
            sel[i] = sc[i] + bias[i];                 // score + expert_bias (selection only)
            used[i] = false;
        }
        int   idx[TOPK];
        float wv[TOPK];
        float sum = 0.f;
        for (int k = 0; k < TOPK; k++) {
            int best = -1; float bv = -1e30f;
            for (int i = 0; i < NE; i++)
                if (!used[i] && sel[i] > bv) { bv = sel[i]; best = i; }  // stable: earliest index on tie
            used[best] = true; idx[k] = best; wv[k] = sc[best]; sum += sc[best];
        }
        float inv = ROUTE_SCALE / sum;
        for (int k = 0; k < TOPK; k++) {
            g_topk_idx[t * TOPK + k] = idx[k];
            g_topk_wt[t * TOPK + k]  = wv[k] * inv;
            atomicAdd(&g_counts[idx[k]], 1);
        }
    }
}

// ---------------- K2: padded prefix sums + tile->expert map ---------------
__global__ void k_offsets() {
    if (threadIdx.x == 0 && blockIdx.x == 0) {
        g_counts[NE] = T_TOK;  // shared expert handles every token
        int off = 0;
        for (int e = 0; e <= NE; e++) {
            g_offsets[e] = off;
            int tiles = (g_counts[e] + 63) >> 6;
            for (int j = 0; j < tiles; j++) g_tile_expert[(off >> 6) + j] = e;
            off += tiles << 6;
        }
        g_offsets[NE + 1] = off;
    }
}

// ---------------- K3: scatter tokens into expert segments -----------------
__global__ void k_scatter() {
    int t = blockIdx.x * blockDim.x + threadIdx.x;
    if (t >= T_TOK) return;
    for (int k = 0; k < TOPK; k++) {
        int e = g_topk_idx[t * TOPK + k];
        int pos = atomicAdd(&g_fill[e], 1);
        int r = g_offsets[e] + pos;
        g_row_token[r] = t;
        g_row_wt[r] = g_topk_wt[t * TOPK + k];
        g_token_rows[t * 9 + k] = r;
    }
    int r = g_offsets[NE] + t;   // shared expert row, weight 1
    g_row_token[r] = t;
    g_row_wt[r] = 1.f;
    g_token_rows[t * 9 + 8] = r;
}

// ---------------- K4: fused gate+up GEMM + SwiGLU -> g_H ------------------
// Tile: BM=64 rows (dispatch rows), BN=64 (intermediate dims), BK=16.
// 256 threads; each thread: 4x4 outputs for BOTH gate and up.
__global__ void __launch_bounds__(256) k_gemm1(const float* __restrict__ x,
                                               const float* __restrict__ w_gate,
                                               const float* __restrict__ w_up,
                                               const float* __restrict__ sh_gate,
                                               const float* __restrict__ sh_up) {
    int e = g_tile_expert[blockIdx.x];
    if (e < 0) return;
    const float* wg = (e < NE) ? (w_gate + (size_t)e * NI * DHID) : sh_gate;
    const float* wu = (e < NE) ? (w_up   + (size_t)e * NI * DHID) : sh_up;

    __shared__ __align__(16) float Xs[16][64];
    __shared__ __align__(16) float Gs[16][64];
    __shared__ __align__(16) float Us[16][64];

    int tid = threadIdx.x;
    int tx = tid & 15, ty = tid >> 4;
    int row_base = blockIdx.x << 6;
    int col_base = blockIdx.y << 6;

    int lrow = tid >> 2;            // 0..63
    int lk   = (tid & 3) << 2;      // 0,4,8,12
    int tok = g_row_token[row_base + lrow];
    const float* xrow = x  + (size_t)tok * DHID;
    const float* grow = wg + (size_t)(col_base + lrow) * DHID;
    const float* urow = wu + (size_t)(col_base + lrow) * DHID;

    float ag[4][4] = {}, au[4][4] = {};

    for (int k0 = 0; k0 < DHID; k0 += 16) {
        float4 xv = *(const float4*)(xrow + k0 + lk);
        float4 gv = *(const float4*)(grow + k0 + lk);
        float4 uv = *(const float4*)(urow + k0 + lk);
        __syncthreads();   // previous iter finished reading smem
        Xs[lk + 0][lrow] = xv.x; Xs[lk + 1][lrow] = xv.y;
        Xs[lk + 2][lrow] = xv.z; Xs[lk + 3][lrow] = xv.w;
        Gs[lk + 0][lrow] = gv.x; Gs[lk + 1][lrow] = gv.y;
        Gs[lk + 2][lrow] = gv.z; Gs[lk + 3][lrow] = gv.w;
        Us[lk + 0][lrow] = uv.x; Us[lk + 1][lrow] = uv.y;
        Us[lk + 2][lrow] = uv.z; Us[lk + 3][lrow] = uv.w;
        __syncthreads();
#pragma unroll
        for (int kk = 0; kk < 16; kk++) {
            float4 xa = *(const float4*)&Xs[kk][ty << 2];
            float4 ga = *(const float4*)&Gs[kk][tx << 2];
            float4 ua = *(const float4*)&Us[kk][tx << 2];
            float xr[4] = {xa.x, xa.y, xa.z, xa.w};
            float gr[4] = {ga.x, ga.y, ga.z, ga.w};
            float ur[4] = {ua.x, ua.y, ua.z, ua.w};
#pragma unroll
            for (int jj = 0; jj < 4; jj++)
#pragma unroll
                for (int j = 0; j < 4; j++) {
                    ag[jj][j] += xr[jj] * gr[j];
                    au[jj][j] += xr[jj] * ur[j];
                }
        }
    }

#pragma unroll
    for (int jj = 0; jj < 4; jj++) {
        int r = row_base + (ty << 2) + jj;
        float4 h;
        float hg, hu;
        hg = ag[jj][0]; hu = au[jj][0]; h.x = hg * hu / (1.f + __expf(-hg));
        hg = ag[jj][1]; hu = au[jj][1]; h.y = hg * hu / (1.f + __expf(-hg));
        hg = ag[jj][2]; hu = au[jj][2]; h.z = hg * hu / (1.f + __expf(-hg));
        hg = ag[jj][3]; hu = au[jj][3]; h.w = hg * hu / (1.f + __expf(-hg));
        *(float4*)&g_H[(size_t)r * NI + col_base + (tx << 2)] = h;
    }
}

// ---------------- K5: down GEMM -> g_Y (pre-scaled by combine weight) -----
// Tile: BM=64 rows, BN=128 (D dims), BK=16. 256 threads; 8x4 per thread.
__global__ void __launch_bounds__(256) k_gemm2(const float* __restrict__ w_down,
                                               const float* __restrict__ sh_down) {
    int e = g_tile_expert[blockIdx.x];
    if (e < 0) return;
    const float* wd = (e < NE) ? (w_down + (size_t)e * DHID * NI) : sh_down;

    __shared__ __align__(16) float Hs[16][64];
    __shared__ __align__(16) float Ws[16][128];

    int tid = threadIdx.x;
    int tx = tid & 31, ty = tid >> 5;     // cols tx*4, rows ty*8..ty*8+7
    int row_base = blockIdx.x << 6;
    int col_base = blockIdx.y << 7;

    int lrow = tid >> 2;                  // 0..63 (H rows)
    int lk   = (tid & 3) << 2;
    const float* hrow  = g_H + (size_t)(row_base + lrow) * NI;
    int wr0 = tid >> 2;                   // 0..63
    int wr1 = 64 + (tid >> 2);            // 64..127
    const float* wrow0 = wd + (size_t)(col_base + wr0) * NI;
    const float* wrow1 = wd + (size_t)(col_base + wr1) * NI;

    float acc[8][4] = {};

    for (int k0 = 0; k0 < NI; k0 += 16) {
        float4 hv = *(const float4*)(hrow  + k0 + lk);
        float4 w0 = *(const float4*)(wrow0 + k0 + lk);
        float4 w1 = *(const float4*)(wrow1 + k0 + lk);
        __syncthreads();
        Hs[lk + 0][lrow] = hv.x; Hs[lk + 1][lrow] = hv.y;
        Hs[lk + 2][lrow] = hv.z; Hs[lk + 3][lrow] = hv.w;
        Ws[lk + 0][wr0] = w0.x; Ws[lk + 1][wr0] = w0.y;
        Ws[lk + 2][wr0] = w0.z; Ws[lk + 3][wr0] = w0.w;
        Ws[lk + 0][wr1] = w1.x; Ws[lk + 1][wr1] = w1.y;
        Ws[lk + 2][wr1] = w1.z; Ws[lk + 3][wr1] = w1.w;
        __syncthreads();
#pragma unroll
        for (int kk = 0; kk < 16; kk++) {
            float4 wv = *(const float4*)&Ws[kk][tx << 2];
            float4 ha = *(const float4*)&Hs[kk][ty << 3];
            float4 hb = *(const float4*)&Hs[kk][(ty << 3) + 4];
            float wrg[4] = {wv.x, wv.y, wv.z, wv.w};
            float hr[8]  = {ha.x, ha.y, ha.z, ha.w, hb.x, hb.y, hb.z, hb.w};
#pragma unroll
            for (int jj = 0; jj < 8; jj++)
#pragma unroll
                for (int j = 0; j < 4; j++)
                    acc[jj][j] += hr[jj] * wrg[j];
        }
    }

#pragma unroll
    for (int jj = 0; jj < 8; jj++) {
        int r = row_base + (ty << 3) + jj;
        float wt = g_row_wt[r];
        float4 o;
        o.x = acc[jj][0] * wt; o.y = acc[jj][1] * wt;
        o.z = acc[jj][2] * wt; o.w = acc[jj][3] * wt;
        *(float4*)&g_Y[(size_t)r * DHID + col_base + (tx << 2)] = o;
    }
}

// ---------------- K6: deterministic combine (9 rows per token) ------------
__global__ void __launch_bounds__(256) k_combine(float* __restrict__ out) {
    int t = blockIdx.x, tid = threadIdx.x;
    int d0 = tid << 2;
    float4 acc = make_float4(0.f, 0.f, 0.f, 0.f);
#pragma unroll
    for (int k = 0; k < 9; k++) {
        int r = g_token_rows[t * 9 + k];
        float4 v = *(const float4*)&g_Y[(size_t)r * DHID + d0];
        acc.x += v.x; acc.y += v.y; acc.z += v.z; acc.w += v.w;
    }
    *(float4*)&out[(size_t)t * DHID + d0] = acc;
}

// ---------------- launch ---------------------------------------------------
extern "C" void kernel_launch(void* const* d_in, const int* in_sizes, int n_in,
                              void* d_out, int out_size) {
    const float* x        = (const float*)d_in[0];
    const float* gate_w   = (const float*)d_in[1];
    const float* ebias    = (const float*)d_in[2];
    const float* w_gate   = (const float*)d_in[3];
    const float* w_up     = (const float*)d_in[4];
    const float* w_down   = (const float*)d_in[5];
    const float* sh_gate  = (const float*)d_in[6];
    const float* sh_up    = (const float*)d_in[7];
    const float* sh_down  = (const float*)d_in[8];
    float* out = (float*)d_out;

    k_init<<<(ROWS_CAP + 255) / 256, 256>>>();
    k_route<<<T_TOK, 128>>>(x, gate_w, ebias);
    k_offsets<<<1, 32>>>();
    k_scatter<<<(T_TOK + 255) / 256, 256>>>();
    k_gemm1<<<dim3(ROW_TILES, NI / 64), 256>>>(x, w_gate, w_up, sh_gate, sh_up);
    k_gemm2<<<dim3(ROW_TILES, DHID / 128), 256>>>(w_down, sh_down);
    k_combine<<<T_TOK, 256>>>(out);
}

// round 3
// speedup vs baseline: 1.7594x; 1.7594x over previous
#include <cuda_runtime.h>
#include <cuda_bf16.h>
#include <math.h>
#include <stdint.h>

#define T_TOK 1024
#define DHID 1024
#define NE 16
#define TOPK 8
#define NI 1024
#define ROUTE_SCALE 2.826f

#define ROW_TILES 88
#define ROWS_CAP (ROW_TILES * 128)   // 11264 >= 8192 + 16*127 + 1024

// 128B-row swizzle: chunk(16B) ^= row&7
#define SW(o) ((o) ^ (((o) >> 3) & 0x70))

// ---------------- scratch ----------------
__device__ uint32_t g_Hil[(size_t)ROWS_CAP * NI];   // packed bf16 (hi | lo<<16)
__device__ float    g_Y[(size_t)ROWS_CAP * DHID];
__device__ int      g_row_token[ROWS_CAP];
__device__ float    g_row_wt[ROWS_CAP];
__device__ int      g_tile_expert[ROW_TILES];
__device__ int      g_token_rows[T_TOK * 9];
__device__ int      g_counts[NE + 1];
__device__ int      g_fill[NE + 1];
__device__ int      g_offsets[NE + 2];
__device__ int      g_topk_idx[T_TOK * TOPK];
__device__ float    g_topk_wt[T_TOK * TOPK];

// ---------------- helpers ----------------
__device__ __forceinline__ uint32_t smem_u32(const void* p) {
    uint32_t a;
    asm("{ .reg .u64 t; cvta.to.shared.u64 t, %1; cvt.u32.u64 %0, t; }" : "=r"(a) : "l"(p));
    return a;
}
__device__ __forceinline__ void ldsm4(uint32_t (&r)[4], uint32_t addr) {
    asm volatile("ldmatrix.sync.aligned.m8n8.x4.shared.b16 {%0,%1,%2,%3}, [%4];"
                 : "=r"(r[0]), "=r"(r[1]), "=r"(r[2]), "=r"(r[3]) : "r"(addr));
}
__device__ __forceinline__ void mma_bf16(float (&d)[4], const uint32_t (&a)[4],
                                         uint32_t b0, uint32_t b1) {
    asm volatile("mma.sync.aligned.m16n8k16.row.col.f32.bf16.bf16.f32 "
                 "{%0,%1,%2,%3}, {%4,%5,%6,%7}, {%8,%9}, {%0,%1,%2,%3};"
                 : "+f"(d[0]), "+f"(d[1]), "+f"(d[2]), "+f"(d[3])
                 : "r"(a[0]), "r"(a[1]), "r"(a[2]), "r"(a[3]), "r"(b0), "r"(b1));
}
// split float4 -> bf16 hi/lo pairs, store 8B each into swizzled smem planes
__device__ __forceinline__ void sts_split4(char* smem, uint32_t oh, uint32_t ol,
                                           int r, int c, float4 v) {
    uint32_t boff = (uint32_t)(r * 128 + c * 2);
    uint32_t sw = SW(boff);
    __nv_bfloat16 h0 = __float2bfloat16(v.x), h1 = __float2bfloat16(v.y);
    __nv_bfloat16 h2 = __float2bfloat16(v.z), h3 = __float2bfloat16(v.w);
    uint2 hp;
    hp.x = (uint32_t)__bfloat16_as_ushort(h0) | ((uint32_t)__bfloat16_as_ushort(h1) << 16);
    hp.y = (uint32_t)__bfloat16_as_ushort(h2) | ((uint32_t)__bfloat16_as_ushort(h3) << 16);
    *(uint2*)(smem + oh + sw) = hp;
    __nv_bfloat16 l0 = __float2bfloat16(v.x - __bfloat162float(h0));
    __nv_bfloat16 l1 = __float2bfloat16(v.y - __bfloat162float(h1));
    __nv_bfloat16 l2 = __float2bfloat16(v.z - __bfloat162float(h2));
    __nv_bfloat16 l3 = __float2bfloat16(v.w - __bfloat162float(h3));
    uint2 lp;
    lp.x = (uint32_t)__bfloat16_as_ushort(l0) | ((uint32_t)__bfloat16_as_ushort(l1) << 16);
    lp.y = (uint32_t)__bfloat16_as_ushort(l2) | ((uint32_t)__bfloat16_as_ushort(l3) << 16);
    *(uint2*)(smem + ol + sw) = lp;
}
__device__ __forceinline__ uint32_t pack_hilo(float h) {
    __nv_bfloat16 hi = __float2bfloat16(h);
    __nv_bfloat16 lo = __float2bfloat16(h - __bfloat162float(hi));
    return (uint32_t)__bfloat16_as_ushort(hi) | ((uint32_t)__bfloat16_as_ushort(lo) << 16);
}

// ---------------- K0: init ----------------
__global__ void k_init() {
    int i = blockIdx.x * blockDim.x + threadIdx.x;
    if (i < ROWS_CAP) { g_row_token[i] = 0; g_row_wt[i] = 0.f; }
    if (i < ROW_TILES) g_tile_expert[i] = -1;
    if (i < NE + 1) { g_counts[i] = 0; g_fill[i] = 0; }
}

// ---------------- K1: routing ----------------
__global__ void __launch_bounds__(128) k_route(const float* __restrict__ x,
                                               const float* __restrict__ gw,
                                               const float* __restrict__ bias) {
    __shared__ float xs[DHID];
    __shared__ float gates[NE];
    int t = blockIdx.x, tid = threadIdx.x;
    for (int i = tid; i < DHID; i += 128) xs[i] = x[(size_t)t * DHID + i];
    __syncthreads();
    int e = tid >> 3, p = tid & 7;
    const float* w = gw + e * DHID + p * 128;
    const float* xv = xs + p * 128;
    float s = 0.f;
#pragma unroll 8
    for (int d = 0; d < 128; d++) s += xv[d] * w[d];
    s += __shfl_down_sync(0xffffffffu, s, 4, 8);
    s += __shfl_down_sync(0xffffffffu, s, 2, 8);
    s += __shfl_down_sync(0xffffffffu, s, 1, 8);
    if (p == 0) gates[e] = s;
    __syncthreads();
    if (tid == 0) {
        float sc[NE], sel[NE];
        bool used[NE];
        for (int i = 0; i < NE; i++) {
            sc[i] = 1.f / (1.f + expf(-gates[i]));
            sel[i] = sc[i] + bias[i];
            used[i] = false;
        }
        int idx[TOPK]; float wv[TOPK]; float sum = 0.f;
        for (int k = 0; k < TOPK; k++) {
            int best = -1; float bv = -1e30f;
            for (int i = 0; i < NE; i++)
                if (!used[i] && sel[i] > bv) { bv = sel[i]; best = i; }
            used[best] = true; idx[k] = best; wv[k] = sc[best]; sum += sc[best];
        }
        float inv = ROUTE_SCALE / sum;
        for (int k = 0; k < TOPK; k++) {
            g_topk_idx[t * TOPK + k] = idx[k];
            g_topk_wt[t * TOPK + k] = wv[k] * inv;
            atomicAdd(&g_counts[idx[k]], 1);
        }
    }
}

// ---------------- K2: offsets (pad 128) ----------------
__global__ void k_offsets() {
    if (threadIdx.x == 0 && blockIdx.x == 0) {
        g_counts[NE] = T_TOK;
        int off = 0;
        for (int e = 0; e <= NE; e++) {
            g_offsets[e] = off;
            int tiles = (g_counts[e] + 127) >> 7;
            for (int j = 0; j < tiles; j++) g_tile_expert[(off >> 7) + j] = e;
            off += tiles << 7;
        }
        g_offsets[NE + 1] = off;
    }
}

// ---------------- K3: scatter ----------------
__global__ void k_scatter() {
    int t = blockIdx.x * blockDim.x + threadIdx.x;
    if (t >= T_TOK) return;
    for (int k = 0; k < TOPK; k++) {
        int e = g_topk_idx[t * TOPK + k];
        int pos = atomicAdd(&g_fill[e], 1);
        int r = g_offsets[e] + pos;
        g_row_token[r] = t;
        g_row_wt[r] = g_topk_wt[t * TOPK + k];
        g_token_rows[t * 9 + k] = r;
    }
    int r = g_offsets[NE] + t;
    g_row_token[r] = t;
    g_row_wt[r] = 1.f;
    g_token_rows[t * 9 + 8] = r;
}

// ---------------- K4: gemm1 fused gate+up, mma.sync, SwiGLU in regs -------
// Block: 128 rows x 64 cols (each for gate AND up). K stages of 64.
// Smem planes: A_hi, A_lo (128x64), Bg_hi/lo, Bu_hi/lo (64x64).
#define S1_AH 0u
#define S1_AL 16384u
#define S1_GH 32768u
#define S1_GL 40960u
#define S1_UH 49152u
#define S1_UL 57344u
#define SMEM1_BYTES 65536
__global__ void __launch_bounds__(256, 1) k_gemm1(const float* __restrict__ x,
                                                  const float* __restrict__ w_gate,
                                                  const float* __restrict__ w_up,
                                                  const float* __restrict__ sh_gate,
                                                  const float* __restrict__ sh_up) {
    extern __shared__ char smem[];
    int e = g_tile_expert[blockIdx.x];
    if (e < 0) return;
    const float* wg = (e < NE) ? w_gate + (size_t)e * NI * DHID : sh_gate;
    const float* wu = (e < NE) ? w_up + (size_t)e * NI * DHID : sh_up;

    const int tid = threadIdx.x, wid = tid >> 5, lane = tid & 31;
    const int wm = (wid >> 1) << 5;     // warp row base (0..96)
    const int wn = (wid & 1) << 5;      // warp col base (0 or 32)
    const uint32_t sb = smem_u32(smem);
    const int col_base = blockIdx.y << 6;
    const int rb = blockIdx.x << 7;

    // per-thread load rows (A: r = 16*i + tid/16 ; B: r = 16*i + tid/16, i<4)
    const int arow = tid >> 4;
    const int acol = (tid & 15) << 2;
    int tok[8];
#pragma unroll
    for (int i = 0; i < 8; i++) tok[i] = g_row_token[rb + (i << 4) + arow];

    float ag[2][4][4] = {}, au[2][4][4] = {};

    // ldmatrix lane addressing pieces
    const int lr = lane & 15;            // row within 16
    const int hb = (lane >> 4) << 4;     // 16B half select

    for (int k0 = 0; k0 < DHID; k0 += 64) {
#pragma unroll
        for (int i = 0; i < 8; i++) {
            float4 v = *(const float4*)(x + (size_t)tok[i] * DHID + k0 + acol);
            sts_split4(smem, S1_AH, S1_AL, (i << 4) + arow, acol, v);
        }
#pragma unroll
        for (int i = 0; i < 4; i++) {
            int r = (i << 4) + arow;
            float4 v = *(const float4*)(wg + (size_t)(col_base + r) * DHID + k0 + acol);
            sts_split4(smem, S1_GH, S1_GL, r, acol, v);
            float4 u = *(const float4*)(wu + (size_t)(col_base + r) * DHID + k0 + acol);
            sts_split4(smem, S1_UH, S1_UL, r, acol, u);
        }
        __syncthreads();
#pragma unroll
        for (int ks = 0; ks < 4; ks++) {
            uint32_t ah[2][4], al[2][4];
#pragma unroll
            for (int mt = 0; mt < 2; mt++) {
                uint32_t off = (uint32_t)((wm + (mt << 4) + lr) * 128 + (ks << 5) + hb);
                ldsm4(ah[mt], sb + S1_AH + SW(off));
                ldsm4(al[mt], sb + S1_AL + SW(off));
            }
#pragma unroll
            for (int nt = 0; nt < 2; nt++) {
                uint32_t boff = (uint32_t)((wn + (nt << 4) + lr) * 128 + (ks << 5) + hb);
                uint32_t sw = SW(boff);
                uint32_t gh[4], gl[4], uh[4], ul[4];
                ldsm4(gh, sb + S1_GH + sw);
                ldsm4(gl, sb + S1_GL + sw);
                ldsm4(uh, sb + S1_UH + sw);
                ldsm4(ul, sb + S1_UL + sw);
#pragma unroll
                for (int mt = 0; mt < 2; mt++) {
                    // n-subtile 0: frags {x[0],x[2]}; subtile 1: {x[1],x[3]}
                    mma_bf16(ag[mt][nt * 2 + 0], ah[mt], gh[0], gh[2]);
                    mma_bf16(ag[mt][nt * 2 + 0], ah[mt], gl[0], gl[2]);
                    mma_bf16(ag[mt][nt * 2 + 0], al[mt], gh[0], gh[2]);
                    mma_bf16(ag[mt][nt * 2 + 1], ah[mt], gh[1], gh[3]);
                    mma_bf16(ag[mt][nt * 2 + 1], ah[mt], gl[1], gl[3]);
                    mma_bf16(ag[mt][nt * 2 + 1], al[mt], gh[1], gh[3]);
                    mma_bf16(au[mt][nt * 2 + 0], ah[mt], uh[0], uh[2]);
                    mma_bf16(au[mt][nt * 2 + 0], ah[mt], ul[0], ul[2]);
                    mma_bf16(au[mt][nt * 2 + 0], al[mt], uh[0], uh[2]);
                    mma_bf16(au[mt][nt * 2 + 1], ah[mt], uh[1], uh[3]);
                    mma_bf16(au[mt][nt * 2 + 1], ah[mt], ul[1], ul[3]);
                    mma_bf16(au[mt][nt * 2 + 1], al[mt], uh[1], uh[3]);
                }
            }
        }
        __syncthreads();
    }

    // epilogue: SwiGLU in registers -> packed bf16 hi/lo -> g_Hil
#pragma unroll
    for (int mt = 0; mt < 2; mt++) {
        int r0 = rb + wm + (mt << 4) + (lane >> 2);
#pragma unroll
        for (int nt = 0; nt < 4; nt++) {
            int c = col_base + wn + (nt << 3) + ((lane & 3) << 1);
            float g0 = ag[mt][nt][0], g1 = ag[mt][nt][1];
            float u0 = au[mt][nt][0], u1 = au[mt][nt][1];
            uint2 o;
            o.x = pack_hilo(g0 * u0 / (1.f + __expf(-g0)));
            o.y = pack_hilo(g1 * u1 / (1.f + __expf(-g1)));
            *(uint2*)&g_Hil[(size_t)r0 * NI + c] = o;
            float g2 = ag[mt][nt][2], g3 = ag[mt][nt][3];
            float u2 = au[mt][nt][2], u3 = au[mt][nt][3];
            uint2 o2;
            o2.x = pack_hilo(g2 * u2 / (1.f + __expf(-g2)));
            o2.y = pack_hilo(g3 * u3 / (1.f + __expf(-g3)));
            *(uint2*)&g_Hil[(size_t)(r0 + 8) * NI + c] = o2;
        }
    }
}

// ---------------- K5: gemm2 down-proj, mma.sync ----------------
// Block: 128 rows x 128 cols of D. A unpacked from g_Hil; B = w_down split.
#define S2_AH 0u
#define S2_AL 16384u
#define S2_BH 32768u
#define S2_BL 49152u
#define SMEM2_BYTES 65536
__global__ void __launch_bounds__(256, 1) k_gemm2(const float* __restrict__ w_down,
                                                  const float* __restrict__ sh_down) {
    extern __shared__ char smem[];
    int e = g_tile_expert[blockIdx.x];
    if (e < 0) return;
    const float* wd = (e < NE) ? w_down + (size_t)e * DHID * NI : sh_down;

    const int tid = threadIdx.x, wid = tid >> 5, lane = tid & 31;
    const int wm = (wid >> 1) << 5;
    const int wn = (wid & 1) << 6;      // 0 or 64
    const uint32_t sb = smem_u32(smem);
    const int col_base = blockIdx.y << 7;
    const int rb = blockIdx.x << 7;

    const int arow = tid >> 4;
    const int acol = (tid & 15) << 2;

    float ad[2][8][4] = {};
    const int lr = lane & 15;
    const int hb = (lane >> 4) << 4;

    for (int k0 = 0; k0 < NI; k0 += 64) {
#pragma unroll
        for (int i = 0; i < 8; i++) {
            int r = (i << 4) + arow;
            uint4 p = *(const uint4*)&g_Hil[(size_t)(rb + r) * NI + k0 + acol];
            uint32_t boff = (uint32_t)(r * 128 + acol * 2);
            uint32_t sw = SW(boff);
            uint2 hp, lp;
            hp.x = (p.x & 0xffffu) | ((p.y & 0xffffu) << 16);
            hp.y = (p.z & 0xffffu) | ((p.w & 0xffffu) << 16);
            lp.x = (p.x >> 16) | (p.y & 0xffff0000u);
            lp.y = (p.z >> 16) | (p.w & 0xffff0000u);
            *(uint2*)(smem + S2_AH + sw) = hp;
            *(uint2*)(smem + S2_AL + sw) = lp;
        }
#pragma unroll
        for (int i = 0; i < 8; i++) {
            int r = (i << 4) + arow;
            float4 v = *(const float4*)(wd + (size_t)(col_base + r) * NI + k0 + acol);
            sts_split4(smem, S2_BH, S2_BL, r, acol, v);
        }
        __syncthreads();
#pragma unroll
        for (int ks = 0; ks < 4; ks++) {
            uint32_t ah[2][4], al[2][4];
#pragma unroll
            for (int mt = 0; mt < 2; mt++) {
                uint32_t off = (uint32_t)((wm + (mt << 4) + lr) * 128 + (ks << 5) + hb);
                ldsm4(ah[mt], sb + S2_AH + SW(off));
                ldsm4(al[mt], sb + S2_AL + SW(off));
            }
#pragma unroll
            for (int nt = 0; nt < 4; nt++) {
                uint32_t boff = (uint32_t)((wn + (nt << 4) + lr) * 128 + (ks << 5) + hb);
                uint32_t sw = SW(boff);
                uint32_t bh[4], bl[4];
                ldsm4(bh, sb + S2_BH + sw);
                ldsm4(bl, sb + S2_BL + sw);
#pragma unroll
                for (int mt = 0; mt < 2; mt++) {
                    mma_bf16(ad[mt][nt * 2 + 0], ah[mt], bh[0], bh[2]);
                    mma_bf16(ad[mt][nt * 2 + 0], ah[mt], bl[0], bl[2]);
                    mma_bf16(ad[mt][nt * 2 + 0], al[mt], bh[0], bh[2]);
                    mma_bf16(ad[mt][nt * 2 + 1], ah[mt], bh[1], bh[3]);
                    mma_bf16(ad[mt][nt * 2 + 1], ah[mt], bl[1], bl[3]);
                    mma_bf16(ad[mt][nt * 2 + 1], al[mt], bh[1], bh[3]);
                }
            }
        }
        __syncthreads();
    }

    // epilogue: scale by combine weight, store fp32
#pragma unroll
    for (int mt = 0; mt < 2; mt++) {
        int r0 = rb + wm + (mt << 4) + (lane >> 2);
        float w0 = g_row_wt[r0], w1 = g_row_wt[r0 + 8];
#pragma unroll
        for (int nt = 0; nt < 8; nt++) {
            int c = col_base + wn + (nt << 3) + ((lane & 3) << 1);
            float2 o0 = make_float2(ad[mt][nt][0] * w0, ad[mt][nt][1] * w0);
            *(float2*)&g_Y[(size_t)r0 * DHID + c] = o0;
            float2 o1 = make_float2(ad[mt][nt][2] * w1, ad[mt][nt][3] * w1);
            *(float2*)&g_Y[(size_t)(r0 + 8) * DHID + c] = o1;
        }
    }
}

// ---------------- K6: combine ----------------
__global__ void __launch_bounds__(256) k_combine(float* __restrict__ out) {
    int t = blockIdx.x, tid = threadIdx.x;
    int d0 = tid << 2;
    float4 acc = make_float4(0.f, 0.f, 0.f, 0.f);
#pragma unroll
    for (int k = 0; k < 9; k++) {
        int r = g_token_rows[t * 9 + k];
        float4 v = *(const float4*)&g_Y[(size_t)r * DHID + d0];
        acc.x += v.x; acc.y += v.y; acc.z += v.z; acc.w += v.w;
    }
    *(float4*)&out[(size_t)t * DHID + d0] = acc;
}

// ---------------- launch ----------------
extern "C" void kernel_launch(void* const* d_in, const int* in_sizes, int n_in,
                              void* d_out, int out_size) {
    const float* x       = (const float*)d_in[0];
    const float* gate_w  = (const float*)d_in[1];
    const float* ebias   = (const float*)d_in[2];
    const float* w_gate  = (const float*)d_in[3];
    const float* w_up    = (const float*)d_in[4];
    const float* w_down  = (const float*)d_in[5];
    const float* sh_gate = (const float*)d_in[6];
    const float* sh_up   = (const float*)d_in[7];
    const float* sh_down = (const float*)d_in[8];
    float* out = (float*)d_out;

    cudaFuncSetAttribute(k_gemm1, cudaFuncAttributeMaxDynamicSharedMemorySize, SMEM1_BYTES);
    cudaFuncSetAttribute(k_gemm2, cudaFuncAttributeMaxDynamicSharedMemorySize, SMEM2_BYTES);

    k_init<<<(ROWS_CAP + 255) / 256, 256>>>();
    k_route<<<T_TOK, 128>>>(x, gate_w, ebias);
    k_offsets<<<1, 32>>>();
    k_scatter<<<(T_TOK + 255) / 256, 256>>>();
    k_gemm1<<<dim3(ROW_TILES, NI / 64), 256, SMEM1_BYTES>>>(x, w_gate, w_up, sh_gate, sh_up);
    k_gemm2<<<dim3(ROW_TILES, DHID / 128), 256, SMEM2_BYTES>>>(w_down, sh_down);
    k_combine<<<T_TOK, 256>>>(out);
}

// round 4
// speedup vs baseline: 2.2822x; 1.2971x over previous
#include <cuda_runtime.h>
#include <cuda_bf16.h>
#include <math.h>
#include <stdint.h>

#define T_TOK 1024
#define DHID 1024
#define NE 16
#define TOPK 8
#define NI 1024
#define ROUTE_SCALE 2.826f

#define ROW_TILES 88
#define ROWS_CAP (ROW_TILES * 128)   // 11264 >= 8192 + 16*127 + 1024
#define WSZ (1u << 20)               // 1024*1024 elements per expert matrix

// 128B-row swizzle on 16B chunks
#define SW(o) ((o) ^ (((o) >> 3) & 0x70))

// ---------------- scratch ----------------
__device__ __nv_bfloat16 g_xh[T_TOK * DHID], g_xl[T_TOK * DHID];
__device__ __nv_bfloat16 g_wgh[17 * WSZ], g_wgl[17 * WSZ];   // gate (16 experts + shared)
__device__ __nv_bfloat16 g_wuh[17 * WSZ], g_wul[17 * WSZ];   // up
__device__ __nv_bfloat16 g_wdh[17 * WSZ], g_wdl[17 * WSZ];   // down
__device__ __nv_bfloat16 g_Hh[(size_t)ROWS_CAP * NI], g_Hl[(size_t)ROWS_CAP * NI];
__device__ float    g_Y[(size_t)ROWS_CAP * DHID];
__device__ int      g_row_token[ROWS_CAP];
__device__ float    g_row_wt[ROWS_CAP];
__device__ int      g_tile_expert[ROW_TILES];
__device__ int      g_token_rows[T_TOK * 9];
__device__ int      g_counts[NE + 1];
__device__ int      g_fill[NE + 1];
__device__ int      g_offsets[NE + 2];
__device__ int      g_topk_idx[T_TOK * TOPK];
__device__ float    g_topk_wt[T_TOK * TOPK];

// ---------------- helpers ----------------
__device__ __forceinline__ uint32_t smem_u32(const void* p) {
    uint32_t a;
    asm("{ .reg .u64 t; cvta.to.shared.u64 t, %1; cvt.u32.u64 %0, t; }" : "=r"(a) : "l"(p));
    return a;
}
__device__ __forceinline__ void ldsm4(uint32_t (&r)[4], uint32_t addr) {
    asm volatile("ldmatrix.sync.aligned.m8n8.x4.shared.b16 {%0,%1,%2,%3}, [%4];"
                 : "=r"(r[0]), "=r"(r[1]), "=r"(r[2]), "=r"(r[3]) : "r"(addr));
}
__device__ __forceinline__ void mma_bf16(float (&d)[4], const uint32_t (&a)[4],
                                         uint32_t b0, uint32_t b1) {
    asm volatile("mma.sync.aligned.m16n8k16.row.col.f32.bf16.bf16.f32 "
                 "{%0,%1,%2,%3}, {%4,%5,%6,%7}, {%8,%9}, {%0,%1,%2,%3};"
                 : "+f"(d[0]), "+f"(d[1]), "+f"(d[2]), "+f"(d[3])
                 : "r"(a[0]), "r"(a[1]), "r"(a[2]), "r"(a[3]), "r"(b0), "r"(b1));
}
__device__ __forceinline__ void cpa16(uint32_t dst, const void* src) {
    asm volatile("cp.async.cg.shared.global [%0], [%1], 16;" :: "r"(dst), "l"(src));
}
#define CPA_COMMIT() asm volatile("cp.async.commit_group;" ::: "memory")
#define CPA_WAIT1()  asm volatile("cp.async.wait_group 1;" ::: "memory")
#define CPA_WAIT0()  asm volatile("cp.async.wait_group 0;" ::: "memory")

// ---------------- K-1: fp32 -> bf16 hi/lo split ----------------
__global__ void __launch_bounds__(256) k_split(const float* __restrict__ src,
                                               __nv_bfloat16* __restrict__ hi,
                                               __nv_bfloat16* __restrict__ lo, int n) {
    int i = (blockIdx.x * 256 + threadIdx.x) << 2;
    if (i >= n) return;
    float4 v = *(const float4*)(src + i);
    __nv_bfloat16 h0 = __float2bfloat16(v.x), h1 = __float2bfloat16(v.y);
    __nv_bfloat16 h2 = __float2bfloat16(v.z), h3 = __float2bfloat16(v.w);
    uint2 hp;
    hp.x = (uint32_t)__bfloat16_as_ushort(h0) | ((uint32_t)__bfloat16_as_ushort(h1) << 16);
    hp.y = (uint32_t)__bfloat16_as_ushort(h2) | ((uint32_t)__bfloat16_as_ushort(h3) << 16);
    *(uint2*)&hi[i] = hp;
    __nv_bfloat16 l0 = __float2bfloat16(v.x - __bfloat162float(h0));
    __nv_bfloat16 l1 = __float2bfloat16(v.y - __bfloat162float(h1));
    __nv_bfloat16 l2 = __float2bfloat16(v.z - __bfloat162float(h2));
    __nv_bfloat16 l3 = __float2bfloat16(v.w - __bfloat162float(h3));
    uint2 lp;
    lp.x = (uint32_t)__bfloat16_as_ushort(l0) | ((uint32_t)__bfloat16_as_ushort(l1) << 16);
    lp.y = (uint32_t)__bfloat16_as_ushort(l2) | ((uint32_t)__bfloat16_as_ushort(l3) << 16);
    *(uint2*)&lo[i] = lp;
}

// ---------------- K0: init ----------------
__global__ void k_init() {
    int i = blockIdx.x * blockDim.x + threadIdx.x;
    if (i < ROWS_CAP) { g_row_token[i] = 0; g_row_wt[i] = 0.f; }
    if (i < ROW_TILES) g_tile_expert[i] = -1;
    if (i < NE + 1) { g_counts[i] = 0; g_fill[i] = 0; }
}

// ---------------- K1: routing ----------------
__global__ void __launch_bounds__(128) k_route(const float* __restrict__ x,
                                               const float* __restrict__ gw,
                                               const float* __restrict__ bias) {
    __shared__ float xs[DHID];
    __shared__ float gates[NE];
    int t = blockIdx.x, tid = threadIdx.x;
    for (int i = tid; i < DHID; i += 128) xs[i] = x[(size_t)t * DHID + i];
    __syncthreads();
    int e = tid >> 3, p = tid & 7;
    const float* w = gw + e * DHID + p * 128;
    const float* xv = xs + p * 128;
    float s = 0.f;
#pragma unroll 8
    for (int d = 0; d < 128; d++) s += xv[d] * w[d];
    s += __shfl_down_sync(0xffffffffu, s, 4, 8);
    s += __shfl_down_sync(0xffffffffu, s, 2, 8);
    s += __shfl_down_sync(0xffffffffu, s, 1, 8);
    if (p == 0) gates[e] = s;
    __syncthreads();
    if (tid == 0) {
        float sc[NE], sel[NE];
        bool used[NE];
        for (int i = 0; i < NE; i++) {
            sc[i] = 1.f / (1.f + expf(-gates[i]));
            sel[i] = sc[i] + bias[i];
            used[i] = false;
        }
        int idx[TOPK]; float wv[TOPK]; float sum = 0.f;
        for (int k = 0; k < TOPK; k++) {
            int best = -1; float bv = -1e30f;
            for (int i = 0; i < NE; i++)
                if (!used[i] && sel[i] > bv) { bv = sel[i]; best = i; }
            used[best] = true; idx[k] = best; wv[k] = sc[best]; sum += sc[best];
        }
        float inv = ROUTE_SCALE / sum;
        for (int k = 0; k < TOPK; k++) {
            g_topk_idx[t * TOPK + k] = idx[k];
            g_topk_wt[t * TOPK + k] = wv[k] * inv;
            atomicAdd(&g_counts[idx[k]], 1);
        }
    }
}

// ---------------- K2: offsets (pad 128) ----------------
__global__ void k_offsets() {
    if (threadIdx.x == 0 && blockIdx.x == 0) {
        g_counts[NE] = T_TOK;
        int off = 0;
        for (int e = 0; e <= NE; e++) {
            g_offsets[e] = off;
            int tiles = (g_counts[e] + 127) >> 7;
            for (int j = 0; j < tiles; j++) g_tile_expert[(off >> 7) + j] = e;
            off += tiles << 7;
        }
        g_offsets[NE + 1] = off;
    }
}

// ---------------- K3: scatter ----------------
__global__ void k_scatter() {
    int t = blockIdx.x * blockDim.x + threadIdx.x;
    if (t >= T_TOK) return;
    for (int k = 0; k < TOPK; k++) {
        int e = g_topk_idx[t * TOPK + k];
        int pos = atomicAdd(&g_fill[e], 1);
        int r = g_offsets[e] + pos;
        g_row_token[r] = t;
        g_row_wt[r] = g_topk_wt[t * TOPK + k];
        g_token_rows[t * 9 + k] = r;
    }
    int r = g_offsets[NE] + t;
    g_row_token[r] = t;
    g_row_wt[r] = 1.f;
    g_token_rows[t * 9 + 8] = r;
}

// ---------------- K4: gemm1 (gate+up fused, cp.async pipelined) -----------
// Stage planes (bytes): AH 0, AL 16384, GH 32768, GL 40960, UH 49152, UL 57344
#define STG1 65536u
#define SMEM1_BYTES (2 * STG1)
__global__ void __launch_bounds__(256, 1) k_gemm1() {
    extern __shared__ char smem[];
    int e = g_tile_expert[blockIdx.x];
    if (e < 0) return;
    const __nv_bfloat16* wgh = g_wgh + ((size_t)e << 20);
    const __nv_bfloat16* wgl = g_wgl + ((size_t)e << 20);
    const __nv_bfloat16* wuh = g_wuh + ((size_t)e << 20);
    const __nv_bfloat16* wul = g_wul + ((size_t)e << 20);

    const int tid = threadIdx.x, wid = tid >> 5, lane = tid & 31;
    const int wm = (wid >> 1) << 5;
    const int wn = (wid & 1) << 5;
    const uint32_t sb = smem_u32(smem);
    const int col_base = blockIdx.y << 6;
    const int rb = blockIdx.x << 7;

    // cp.async row/chunk assignment: thread t covers rows (t>>3)+32*i, chunk t&7
    const int crow = tid >> 3;
    const int cc8 = tid & 7;
    int tok4[4];
#pragma unroll
    for (int i = 0; i < 4; i++) tok4[i] = g_row_token[rb + crow + (i << 5)];

    // issue one stage of loads
    auto issue = [&](int stg, int k0) {
        uint32_t base = sb + (uint32_t)stg * STG1;
#pragma unroll
        for (int i = 0; i < 4; i++) {
            int r = crow + (i << 5);
            uint32_t boff = SW((uint32_t)(r * 128 + cc8 * 16));
            size_t goff = (size_t)tok4[i] * DHID + k0 + cc8 * 8;
            cpa16(base + 0u + boff, g_xh + goff);
            cpa16(base + 16384u + boff, g_xl + goff);
        }
#pragma unroll
        for (int i = 0; i < 2; i++) {
            int r = crow + (i << 5);
            if (r < 64) {
                uint32_t boff = SW((uint32_t)(r * 128 + cc8 * 16));
                size_t goff = (size_t)(col_base + r) * DHID + k0 + cc8 * 8;
                cpa16(base + 32768u + boff, wgh + goff);
                cpa16(base + 40960u + boff, wgl + goff);
                cpa16(base + 49152u + boff, wuh + goff);
                cpa16(base + 57344u + boff, wul + goff);
            }
        }
        CPA_COMMIT();
    };

    float ag[2][4][4] = {}, au[2][4][4] = {};
    const int lr = lane & 15;
    const int hb = (lane >> 4) << 4;

    issue(0, 0);
    const int NK = DHID / 64;
    for (int kc = 0; kc < NK; kc++) {
        if (kc + 1 < NK) issue((kc + 1) & 1, (kc + 1) << 6);
        if (kc + 1 < NK) { CPA_WAIT1(); } else { CPA_WAIT0(); }
        __syncthreads();
        uint32_t base = sb + (uint32_t)(kc & 1) * STG1;
#pragma unroll
        for (int ks = 0; ks < 4; ks++) {
            uint32_t ah[2][4], al[2][4];
#pragma unroll
            for (int mt = 0; mt < 2; mt++) {
                uint32_t off = SW((uint32_t)((wm + (mt << 4) + lr) * 128 + (ks << 5) + hb));
                ldsm4(ah[mt], base + 0u + off);
                ldsm4(al[mt], base + 16384u + off);
            }
#pragma unroll
            for (int nt = 0; nt < 2; nt++) {
                uint32_t off = SW((uint32_t)((wn + (nt << 4) + lr) * 128 + (ks << 5) + hb));
                uint32_t gh[4], gl[4], uh[4], ul[4];
                ldsm4(gh, base + 32768u + off);
                ldsm4(gl, base + 40960u + off);
                ldsm4(uh, base + 49152u + off);
                ldsm4(ul, base + 57344u + off);
#pragma unroll
                for (int mt = 0; mt < 2; mt++) {
                    mma_bf16(ag[mt][nt * 2 + 0], ah[mt], gh[0], gh[2]);
                    mma_bf16(ag[mt][nt * 2 + 0], ah[mt], gl[0], gl[2]);
                    mma_bf16(ag[mt][nt * 2 + 0], al[mt], gh[0], gh[2]);
                    mma_bf16(ag[mt][nt * 2 + 1], ah[mt], gh[1], gh[3]);
                    mma_bf16(ag[mt][nt * 2 + 1], ah[mt], gl[1], gl[3]);
                    mma_bf16(ag[mt][nt * 2 + 1], al[mt], gh[1], gh[3]);
                    mma_bf16(au[mt][nt * 2 + 0], ah[mt], uh[0], uh[2]);
                    mma_bf16(au[mt][nt * 2 + 0], ah[mt], ul[0], ul[2]);
                    mma_bf16(au[mt][nt * 2 + 0], al[mt], uh[0], uh[2]);
                    mma_bf16(au[mt][nt * 2 + 1], ah[mt], uh[1], uh[3]);
                    mma_bf16(au[mt][nt * 2 + 1], ah[mt], ul[1], ul[3]);
                    mma_bf16(au[mt][nt * 2 + 1], al[mt], uh[1], uh[3]);
                }
            }
        }
        __syncthreads();
    }

    // epilogue: SwiGLU in regs -> Hhi/Hlo planes
#pragma unroll
    for (int mt = 0; mt < 2; mt++) {
        int r0 = rb + wm + (mt << 4) + (lane >> 2);
#pragma unroll
        for (int nt = 0; nt < 4; nt++) {
            int c = col_base + wn + (nt << 3) + ((lane & 3) << 1);
#pragma unroll
            for (int half = 0; half < 2; half++) {
                int r = r0 + half * 8;
                float g0 = ag[mt][nt][half * 2 + 0], g1 = ag[mt][nt][half * 2 + 1];
                float u0 = au[mt][nt][half * 2 + 0], u1 = au[mt][nt][half * 2 + 1];
                float h0 = g0 * u0 / (1.f + __expf(-g0));
                float h1 = g1 * u1 / (1.f + __expf(-g1));
                __nv_bfloat16 h0h = __float2bfloat16(h0), h1h = __float2bfloat16(h1);
                uint32_t hp = (uint32_t)__bfloat16_as_ushort(h0h)
                            | ((uint32_t)__bfloat16_as_ushort(h1h) << 16);
                *(uint32_t*)&g_Hh[(size_t)r * NI + c] = hp;
                __nv_bfloat16 l0 = __float2bfloat16(h0 - __bfloat162float(h0h));
                __nv_bfloat16 l1 = __float2bfloat16(h1 - __bfloat162float(h1h));
                uint32_t lp = (uint32_t)__bfloat16_as_ushort(l0)
                            | ((uint32_t)__bfloat16_as_ushort(l1) << 16);
                *(uint32_t*)&g_Hl[(size_t)r * NI + c] = lp;
            }
        }
    }
}

// ---------------- K5: gemm2 (down proj, cp.async pipelined) ----------------
// Stage planes: AH 0, AL 16384, BH 32768, BL 49152
#define STG2 65536u
#define SMEM2_BYTES (2 * STG2)
__global__ void __launch_bounds__(256, 1) k_gemm2() {
    extern __shared__ char smem[];
    int e = g_tile_expert[blockIdx.x];
    if (e < 0) return;
    const __nv_bfloat16* wdh = g_wdh + ((size_t)e << 20);
    const __nv_bfloat16* wdl = g_wdl + ((size_t)e << 20);

    const int tid = threadIdx.x, wid = tid >> 5, lane = tid & 31;
    const int wm = (wid >> 1) << 5;
    const int wn = (wid & 1) << 6;
    const uint32_t sb = smem_u32(smem);
    const int col_base = blockIdx.y << 7;
    const int rb = blockIdx.x << 7;

    const int crow = tid >> 3;
    const int cc8 = tid & 7;

    auto issue = [&](int stg, int k0) {
        uint32_t base = sb + (uint32_t)stg * STG2;
#pragma unroll
        for (int i = 0; i < 4; i++) {
            int r = crow + (i << 5);
            uint32_t boff = SW((uint32_t)(r * 128 + cc8 * 16));
            size_t aoff = (size_t)(rb + r) * NI + k0 + cc8 * 8;
            cpa16(base + 0u + boff, g_Hh + aoff);
            cpa16(base + 16384u + boff, g_Hl + aoff);
            size_t boff2 = (size_t)(col_base + r) * NI + k0 + cc8 * 8;
            cpa16(base + 32768u + boff, wdh + boff2);
            cpa16(base + 49152u + boff, wdl + boff2);
        }
        CPA_COMMIT();
    };

    float ad[2][8][4] = {};
    const int lr = lane & 15;
    const int hb = (lane >> 4) << 4;

    issue(0, 0);
    const int NK = NI / 64;
    for (int kc = 0; kc < NK; kc++) {
        if (kc + 1 < NK) issue((kc + 1) & 1, (kc + 1) << 6);
        if (kc + 1 < NK) { CPA_WAIT1(); } else { CPA_WAIT0(); }
        __syncthreads();
        uint32_t base = sb + (uint32_t)(kc & 1) * STG2;
#pragma unroll
        for (int ks = 0; ks < 4; ks++) {
            uint32_t ah[2][4], al[2][4];
#pragma unroll
            for (int mt = 0; mt < 2; mt++) {
                uint32_t off = SW((uint32_t)((wm + (mt << 4) + lr) * 128 + (ks << 5) + hb));
                ldsm4(ah[mt], base + 0u + off);
                ldsm4(al[mt], base + 16384u + off);
            }
#pragma unroll
            for (int nt = 0; nt < 4; nt++) {
                uint32_t off = SW((uint32_t)((wn + (nt << 4) + lr) * 128 + (ks << 5) + hb));
                uint32_t bh[4], bl[4];
                ldsm4(bh, base + 32768u + off);
                ldsm4(bl, base + 49152u + off);
#pragma unroll
                for (int mt = 0; mt < 2; mt++) {
                    mma_bf16(ad[mt][nt * 2 + 0], ah[mt], bh[0], bh[2]);
                    mma_bf16(ad[mt][nt * 2 + 0], ah[mt], bl[0], bl[2]);
                    mma_bf16(ad[mt][nt * 2 + 0], al[mt], bh[0], bh[2]);
                    mma_bf16(ad[mt][nt * 2 + 1], ah[mt], bh[1], bh[3]);
                    mma_bf16(ad[mt][nt * 2 + 1], ah[mt], bl[1], bl[3]);
                    mma_bf16(ad[mt][nt * 2 + 1], al[mt], bh[1], bh[3]);
                }
            }
        }
        __syncthreads();
    }

#pragma unroll
    for (int mt = 0; mt < 2; mt++) {
        int r0 = rb + wm + (mt << 4) + (lane >> 2);
        float w0 = g_row_wt[r0], w1 = g_row_wt[r0 + 8];
#pragma unroll
        for (int nt = 0; nt < 8; nt++) {
            int c = col_base + wn + (nt << 3) + ((lane & 3) << 1);
            float2 o0 = make_float2(ad[mt][nt][0] * w0, ad[mt][nt][1] * w0);
            *(float2*)&g_Y[(size_t)r0 * DHID + c] = o0;
            float2 o1 = make_float2(ad[mt][nt][2] * w1, ad[mt][nt][3] * w1);
            *(float2*)&g_Y[(size_t)(r0 + 8) * DHID + c] = o1;
        }
    }
}

// ---------------- K6: combine ----------------
__global__ void __launch_bounds__(256) k_combine(float* __restrict__ out) {
    int t = blockIdx.x, tid = threadIdx.x;
    int d0 = tid << 2;
    float4 acc = make_float4(0.f, 0.f, 0.f, 0.f);
#pragma unroll
    for (int k = 0; k < 9; k++) {
        int r = g_token_rows[t * 9 + k];
        float4 v = *(const float4*)&g_Y[(size_t)r * DHID + d0];
        acc.x += v.x; acc.y += v.y; acc.z += v.z; acc.w += v.w;
    }
    *(float4*)&out[(size_t)t * DHID + d0] = acc;
}

// ---------------- launch ----------------
extern "C" void kernel_launch(void* const* d_in, const int* in_sizes, int n_in,
                              void* d_out, int out_size) {
    const float* x       = (const float*)d_in[0];
    const float* gate_w  = (const float*)d_in[1];
    const float* ebias   = (const float*)d_in[2];
    const float* w_gate  = (const float*)d_in[3];
    const float* w_up    = (const float*)d_in[4];
    const float* w_down  = (const float*)d_in[5];
    const float* sh_gate = (const float*)d_in[6];
    const float* sh_up   = (const float*)d_in[7];
    const float* sh_down = (const float*)d_in[8];
    float* out = (float*)d_out;

    cudaFuncSetAttribute(k_gemm1, cudaFuncAttributeMaxDynamicSharedMemorySize, SMEM1_BYTES);
    cudaFuncSetAttribute(k_gemm2, cudaFuncAttributeMaxDynamicSharedMemorySize, SMEM2_BYTES);

    __nv_bfloat16 *xh, *xl, *wgh, *wgl, *wuh, *wul, *wdh, *wdl;
    cudaGetSymbolAddress((void**)&xh, g_xh);  cudaGetSymbolAddress((void**)&xl, g_xl);
    cudaGetSymbolAddress((void**)&wgh, g_wgh); cudaGetSymbolAddress((void**)&wgl, g_wgl);
    cudaGetSymbolAddress((void**)&wuh, g_wuh); cudaGetSymbolAddress((void**)&wul, g_wul);
    cudaGetSymbolAddress((void**)&wdh, g_wdh); cudaGetSymbolAddress((void**)&wdl, g_wdl);

    const int NW = 16 * 1024 * 1024;   // routed weights per matrix
    const int NS = 1024 * 1024;        // shared / x
#define SPLIT(src, h, l, n) k_split<<<((n) / 4 + 255) / 256, 256>>>(src, h, l, n)
    SPLIT(x, xh, xl, T_TOK * DHID);
    SPLIT(w_gate, wgh, wgl, NW);   SPLIT(sh_gate, wgh + (size_t)16 * NS, wgl + (size_t)16 * NS, NS);
    SPLIT(w_up,   wuh, wul, NW);   SPLIT(sh_up,   wuh + (size_t)16 * NS, wul + (size_t)16 * NS, NS);
    SPLIT(w_down, wdh, wdl, NW);   SPLIT(sh_down, wdh + (size_t)16 * NS, wdl + (size_t)16 * NS, NS);
#undef SPLIT

    k_init<<<(ROWS_CAP + 255) / 256, 256>>>();
    k_route<<<T_TOK, 128>>>(x, gate_w, ebias);
    k_offsets<<<1, 32>>>();
    k_scatter<<<(T_TOK + 255) / 256, 256>>>();
    k_gemm1<<<dim3(ROW_TILES, NI / 64), 256, SMEM1_BYTES>>>();
    k_gemm2<<<dim3(ROW_TILES, DHID / 128), 256, SMEM2_BYTES>>>();
    k_combine<<<T_TOK, 256>>>(out);
}

// round 6
// speedup vs baseline: 2.2957x; 1.0059x over previous
#include <cuda_runtime.h>
#include <cuda_bf16.h>
#include <math.h>
#include <stdint.h>

#define T_TOK 1024
#define DHID 1024
#define NE 16
#define TOPK 8
#define NI 1024
#define ROUTE_SCALE 2.826f

#define ROW_TILES 88
#define ROWS_CAP (ROW_TILES * 128)   // 11264 >= 8192 + 16*127 + 1024
#define WSZ (1u << 20)

#define SW(o) ((o) ^ (((o) >> 3) & 0x70))

// ---------------- scratch ----------------
__device__ __nv_bfloat16 g_xh[T_TOK * DHID], g_xl[T_TOK * DHID];
__device__ __nv_bfloat16 g_wgh[17 * WSZ], g_wgl[17 * WSZ];
__device__ __nv_bfloat16 g_wuh[17 * WSZ], g_wul[17 * WSZ];
__device__ __nv_bfloat16 g_wdh[17 * WSZ], g_wdl[17 * WSZ];
__device__ __nv_bfloat16 g_Hh[(size_t)ROWS_CAP * NI], g_Hl[(size_t)ROWS_CAP * NI];
__device__ float    g_Y[(size_t)ROWS_CAP * DHID];
__device__ int      g_row_token[ROWS_CAP];
__device__ float    g_row_wt[ROWS_CAP];
__device__ int      g_tile_expert[ROW_TILES];
__device__ int      g_token_rows[T_TOK * 9];
__device__ int      g_counts[NE + 1];
__device__ int      g_fill[NE + 1];
__device__ int      g_offsets[NE + 2];
__device__ int      g_topk_idx[T_TOK * TOPK];
__device__ float    g_topk_wt[T_TOK * TOPK];

// ---------------- helpers ----------------
__device__ __forceinline__ uint32_t smem_u32(const void* p) {
    uint32_t a;
    asm("{ .reg .u64 t; cvta.to.shared.u64 t, %1; cvt.u32.u64 %0, t; }" : "=r"(a) : "l"(p));
    return a;
}
__device__ __forceinline__ void ldsm4(uint32_t (&r)[4], uint32_t addr) {
    asm volatile("ldmatrix.sync.aligned.m8n8.x4.shared.b16 {%0,%1,%2,%3}, [%4];"
                 : "=r"(r[0]), "=r"(r[1]), "=r"(r[2]), "=r"(r[3]) : "r"(addr));
}
__device__ __forceinline__ void mma_bf16(float (&d)[4], const uint32_t (&a)[4],
                                         uint32_t b0, uint32_t b1) {
    asm volatile("mma.sync.aligned.m16n8k16.row.col.f32.bf16.bf16.f32 "
                 "{%0,%1,%2,%3}, {%4,%5,%6,%7}, {%8,%9}, {%0,%1,%2,%3};"
                 : "+f"(d[0]), "+f"(d[1]), "+f"(d[2]), "+f"(d[3])
                 : "r"(a[0]), "r"(a[1]), "r"(a[2]), "r"(a[3]), "r"(b0), "r"(b1));
}
__device__ __forceinline__ void cpa16(uint32_t dst, const void* src) {
    asm volatile("cp.async.cg.shared.global [%0], [%1], 16;" :: "r"(dst), "l"(src));
}
#define CPA_COMMIT() asm volatile("cp.async.commit_group;" ::: "memory")
#define CPA_WAIT1()  asm volatile("cp.async.wait_group 1;" ::: "memory")
#define CPA_WAIT0()  asm volatile("cp.async.wait_group 0;" ::: "memory")

// ---------------- K-1: merged fp32 -> bf16 hi/lo split (ONE launch) -------
struct SplitArgs {
    const float* src[7];
    __nv_bfloat16* hi[7];
    __nv_bfloat16* lo[7];
    int blk_end[7];   // exclusive block prefix per segment
};
__global__ void __launch_bounds__(256) k_split_all(SplitArgs a) {
    int b = blockIdx.x;
    int s = 0;
    while (b >= a.blk_end[s]) s++;
    int base = s ? a.blk_end[s - 1] : 0;
    size_t i = ((size_t)(b - base) * 256 + threadIdx.x) << 2;
    float4 v = *(const float4*)(a.src[s] + i);
    __nv_bfloat16 h0 = __float2bfloat16(v.x), h1 = __float2bfloat16(v.y);
    __nv_bfloat16 h2 = __float2bfloat16(v.z), h3 = __float2bfloat16(v.w);
    uint2 hp;
    hp.x = (uint32_t)__bfloat16_as_ushort(h0) | ((uint32_t)__bfloat16_as_ushort(h1) << 16);
    hp.y = (uint32_t)__bfloat16_as_ushort(h2) | ((uint32_t)__bfloat16_as_ushort(h3) << 16);
    *(uint2*)&a.hi[s][i] = hp;
    __nv_bfloat16 l0 = __float2bfloat16(v.x - __bfloat162float(h0));
    __nv_bfloat16 l1 = __float2bfloat16(v.y - __bfloat162float(h1));
    __nv_bfloat16 l2 = __float2bfloat16(v.z - __bfloat162float(h2));
    __nv_bfloat16 l3 = __float2bfloat16(v.w - __bfloat162float(h3));
    uint2 lp;
    lp.x = (uint32_t)__bfloat16_as_ushort(l0) | ((uint32_t)__bfloat16_as_ushort(l1) << 16);
    lp.y = (uint32_t)__bfloat16_as_ushort(l2) | ((uint32_t)__bfloat16_as_ushort(l3) << 16);
    *(uint2*)&a.lo[s][i] = lp;
}

// ---------------- K0: init ----------------
__global__ void k_init() {
    int i = blockIdx.x * blockDim.x + threadIdx.x;
    if (i < ROWS_CAP) { g_row_token[i] = 0; g_row_wt[i] = 0.f; }
    if (i < ROW_TILES) g_tile_expert[i] = -1;
    if (i < NE + 1) { g_counts[i] = 0; g_fill[i] = 0; }
}

// ---------------- K1: routing ----------------
__global__ void __launch_bounds__(128) k_route(const float* __restrict__ x,
                                               const float* __restrict__ gw,
                                               const float* __restrict__ bias) {
    __shared__ float xs[DHID];
    __shared__ float gates[NE];
    int t = blockIdx.x, tid = threadIdx.x;
    for (int i = tid; i < DHID; i += 128) xs[i] = x[(size_t)t * DHID + i];
    __syncthreads();
    int e = tid >> 3, p = tid & 7;
    const float* w = gw + e * DHID + p * 128;
    const float* xv = xs + p * 128;
    float s = 0.f;
#pragma unroll 8
    for (int d = 0; d < 128; d++) s += xv[d] * w[d];
    s += __shfl_down_sync(0xffffffffu, s, 4, 8);
    s += __shfl_down_sync(0xffffffffu, s, 2, 8);
    s += __shfl_down_sync(0xffffffffu, s, 1, 8);
    if (p == 0) gates[e] = s;
    __syncthreads();
    if (tid == 0) {
        float sc[NE], sel[NE];
        bool used[NE];
        for (int i = 0; i < NE; i++) {
            sc[i] = 1.f / (1.f + expf(-gates[i]));
            sel[i] = sc[i] + bias[i];
            used[i] = false;
        }
        int idx[TOPK]; float wv[TOPK]; float sum = 0.f;
        for (int k = 0; k < TOPK; k++) {
            int best = -1; float bv = -1e30f;
            for (int i = 0; i < NE; i++)
                if (!used[i] && sel[i] > bv) { bv = sel[i]; best = i; }
            used[best] = true; idx[k] = best; wv[k] = sc[best]; sum += sc[best];
        }
        float inv = ROUTE_SCALE / sum;
        for (int k = 0; k < TOPK; k++) {
            g_topk_idx[t * TOPK + k] = idx[k];
            g_topk_wt[t * TOPK + k] = wv[k] * inv;
            atomicAdd(&g_counts[idx[k]], 1);
        }
    }
}

// ---------------- K2: offsets ----------------
__global__ void k_offsets() {
    if (threadIdx.x == 0 && blockIdx.x == 0) {
        g_counts[NE] = T_TOK;
        int off = 0;
        for (int e = 0; e <= NE; e++) {
            g_offsets[e] = off;
            int tiles = (g_counts[e] + 127) >> 7;
            for (int j = 0; j < tiles; j++) g_tile_expert[(off >> 7) + j] = e;
            off += tiles << 7;
        }
        g_offsets[NE + 1] = off;
    }
}

// ---------------- K3: scatter ----------------
__global__ void k_scatter() {
    int t = blockIdx.x * blockDim.x + threadIdx.x;
    if (t >= T_TOK) return;
    for (int k = 0; k < TOPK; k++) {
        int e = g_topk_idx[t * TOPK + k];
        int pos = atomicAdd(&g_fill[e], 1);
        int r = g_offsets[e] + pos;
        g_row_token[r] = t;
        g_row_wt[r] = g_topk_wt[t * TOPK + k];
        g_token_rows[t * 9 + k] = r;
    }
    int r = g_offsets[NE] + t;
    g_row_token[r] = t;
    g_row_wt[r] = 1.f;
    g_token_rows[t * 9 + 8] = r;
}

// ---------------- K4: gemm1 (BK=32, hi|lo packed rows, 2 CTA/SM) ----------
// Stage (32KB): A 0..16KB (128 rows x [32 hi | 32 lo]), G 16KB..24KB, U 24KB..32KB
#define STG1 32768u
#define SMEM1_BYTES (2 * STG1)
__global__ void __launch_bounds__(256, 2) k_gemm1() {
    extern __shared__ char smem[];
    int e = g_tile_expert[blockIdx.x];
    if (e < 0) return;
    const __nv_bfloat16* wgh = g_wgh + ((size_t)e << 20);
    const __nv_bfloat16* wgl = g_wgl + ((size_t)e << 20);
    const __nv_bfloat16* wuh = g_wuh + ((size_t)e << 20);
    const __nv_bfloat16* wul = g_wul + ((size_t)e << 20);

    const int tid = threadIdx.x, wid = tid >> 5, lane = tid & 31;
    const int wm = (wid >> 1) << 5;
    const int wn = (wid & 1) << 5;
    const uint32_t sb = smem_u32(smem);
    const int col_base = blockIdx.y << 6;
    const int rb = blockIdx.x << 7;

    const int crow = tid >> 3;        // 0..31
    const int cc8 = tid & 7;          // chunk: 0..3 = hi, 4..7 = lo
    int tok4[4];
#pragma unroll
    for (int i = 0; i < 4; i++) tok4[i] = g_row_token[rb + crow + (i << 5)];

    const __nv_bfloat16* xsrc = (cc8 < 4) ? g_xh : g_xl;
    const __nv_bfloat16* gsrc = (cc8 < 4) ? wgh : wgl;
    const __nv_bfloat16* usrc = (cc8 < 4) ? wuh : wul;
    const int ke = (cc8 & 3) << 3;    // k element offset 0,8,16,24

    auto issue = [&](int stg, int k0) {
        uint32_t base = sb + (uint32_t)stg * STG1;
#pragma unroll
        for (int i = 0; i < 4; i++) {
            int r = crow + (i << 5);
            uint32_t boff = SW((uint32_t)(r * 128 + cc8 * 16));
            cpa16(base + boff, xsrc + (size_t)tok4[i] * DHID + k0 + ke);
        }
#pragma unroll
        for (int i = 0; i < 2; i++) {
            int r = crow + (i << 5);
            uint32_t boff = SW((uint32_t)(r * 128 + cc8 * 16));
            size_t go = (size_t)(col_base + r) * DHID + k0 + ke;
            cpa16(base + 16384u + boff, gsrc + go);
            cpa16(base + 24576u + boff, usrc + go);
        }
        CPA_COMMIT();
    };

    float ag[2][4][4] = {}, au[2][4][4] = {};
    const int lr = lane & 15;
    const int hb = (lane >> 4) << 4;

    issue(0, 0);
    const int NK = DHID / 32;
    for (int kc = 0; kc < NK; kc++) {
        if (kc + 1 < NK) issue((kc + 1) & 1, (kc + 1) << 5);
        if (kc + 1 < NK) { CPA_WAIT1(); } else { CPA_WAIT0(); }
        __syncthreads();
        uint32_t base = sb + (uint32_t)(kc & 1) * STG1;
#pragma unroll
        for (int ks = 0; ks < 2; ks++) {
            uint32_t ah[2][4], al[2][4];
#pragma unroll
            for (int mt = 0; mt < 2; mt++) {
                uint32_t row = (uint32_t)((wm + (mt << 4) + lr) * 128);
                ldsm4(ah[mt], base + SW(row + (ks << 5) + hb));
                ldsm4(al[mt], base + SW(row + 64 + (ks << 5) + hb));
            }
#pragma unroll
            for (int nt = 0; nt < 2; nt++) {
                uint32_t row = (uint32_t)((wn + (nt << 4) + lr) * 128);
                uint32_t offh = SW(row + (ks << 5) + hb);
                uint32_t offl = SW(row + 64 + (ks << 5) + hb);
                uint32_t gh[4], gl[4], uh[4], ul[4];
                ldsm4(gh, base + 16384u + offh);
                ldsm4(gl, base + 16384u + offl);
                ldsm4(uh, base + 24576u + offh);
                ldsm4(ul, base + 24576u + offl);
#pragma unroll
                for (int mt = 0; mt < 2; mt++) {
                    mma_bf16(ag[mt][nt * 2 + 0], ah[mt], gh[0], gh[2]);
                    mma_bf16(ag[mt][nt * 2 + 0], ah[mt], gl[0], gl[2]);
                    mma_bf16(ag[mt][nt * 2 + 0], al[mt], gh[0], gh[2]);
                    mma_bf16(ag[mt][nt * 2 + 1], ah[mt], gh[1], gh[3]);
                    mma_bf16(ag[mt][nt * 2 + 1], ah[mt], gl[1], gl[3]);
                    mma_bf16(ag[mt][nt * 2 + 1], al[mt], gh[1], gh[3]);
                    mma_bf16(au[mt][nt * 2 + 0], ah[mt], uh[0], uh[2]);
                    mma_bf16(au[mt][nt * 2 + 0], ah[mt], ul[0], ul[2]);
                    mma_bf16(au[mt][nt * 2 + 0], al[mt], uh[0], uh[2]);
                    mma_bf16(au[mt][nt * 2 + 1], ah[mt], uh[1], uh[3]);
                    mma_bf16(au[mt][nt * 2 + 1], ah[mt], ul[1], ul[3]);
                    mma_bf16(au[mt][nt * 2 + 1], al[mt], uh[1], uh[3]);
                }
            }
        }
        __syncthreads();
    }

    // epilogue: SwiGLU in regs -> Hhi/Hlo planes
#pragma unroll
    for (int mt = 0; mt < 2; mt++) {
        int r0 = rb + wm + (mt << 4) + (lane >> 2);
#pragma unroll
        for (int nt = 0; nt < 4; nt++) {
            int c = col_base + wn + (nt << 3) + ((lane & 3) << 1);
#pragma unroll
            for (int half = 0; half < 2; half++) {
                int r = r0 + half * 8;
                float g0 = ag[mt][nt][half * 2 + 0], g1 = ag[mt][nt][half * 2 + 1];
                float u0 = au[mt][nt][half * 2 + 0], u1 = au[mt][nt][half * 2 + 1];
                float h0 = g0 * u0 / (1.f + __expf(-g0));
                float h1 = g1 * u1 / (1.f + __expf(-g1));
                __nv_bfloat16 h0h = __float2bfloat16(h0), h1h = __float2bfloat16(h1);
                uint32_t hp = (uint32_t)__bfloat16_as_ushort(h0h)
                            | ((uint32_t)__bfloat16_as_ushort(h1h) << 16);
                *(uint32_t*)&g_Hh[(size_t)r * NI + c] = hp;
                __nv_bfloat16 l0 = __float2bfloat16(h0 - __bfloat162float(h0h));
                __nv_bfloat16 l1 = __float2bfloat16(h1 - __bfloat162float(h1h));
                uint32_t lp = (uint32_t)__bfloat16_as_ushort(l0)
                            | ((uint32_t)__bfloat16_as_ushort(l1) << 16);
                *(uint32_t*)&g_Hl[(size_t)r * NI + c] = lp;
            }
        }
    }
}

// ---------------- K5: gemm2 (BK=32, hi|lo packed rows, 2 CTA/SM) ----------
// Stage (32KB): A 0..16KB (128 x [32hi|32lo]), B 16KB..32KB (128 x [32hi|32lo])
#define STG2 32768u
#define SMEM2_BYTES (2 * STG2)
__global__ void __launch_bounds__(256, 2) k_gemm2() {
    extern __shared__ char smem[];
    int e = g_tile_expert[blockIdx.x];
    if (e < 0) return;
    const __nv_bfloat16* wdh = g_wdh + ((size_t)e << 20);
    const __nv_bfloat16* wdl = g_wdl + ((size_t)e << 20);

    const int tid = threadIdx.x, wid = tid >> 5, lane = tid & 31;
    const int wm = (wid >> 1) << 5;
    const int wn = (wid & 1) << 6;
    const uint32_t sb = smem_u32(smem);
    const int col_base = blockIdx.y << 7;
    const int rb = blockIdx.x << 7;

    const int crow = tid >> 3;
    const int cc8 = tid & 7;
    const __nv_bfloat16* asrc = (cc8 < 4) ? g_Hh : g_Hl;
    const __nv_bfloat16* bsrc = (cc8 < 4) ? wdh : wdl;
    const int ke = (cc8 & 3) << 3;

    auto issue = [&](int stg, int k0) {
        uint32_t base = sb + (uint32_t)stg * STG2;
#pragma unroll
        for (int i = 0; i < 4; i++) {
            int r = crow + (i << 5);
            uint32_t boff = SW((uint32_t)(r * 128 + cc8 * 16));
            cpa16(base + boff, asrc + (size_t)(rb + r) * NI + k0 + ke);
            cpa16(base + 16384u + boff, bsrc + (size_t)(col_base + r) * NI + k0 + ke);
        }
        CPA_COMMIT();
    };

    float ad[2][8][4] = {};
    const int lr = lane & 15;
    const int hb = (lane >> 4) << 4;

    issue(0, 0);
    const int NK = NI / 32;
    for (int kc = 0; kc < NK; kc++) {
        if (kc + 1 < NK) issue((kc + 1) & 1, (kc + 1) << 5);
        if (kc + 1 < NK) { CPA_WAIT1(); } else { CPA_WAIT0(); }
        __syncthreads();
        uint32_t base = sb + (uint32_t)(kc & 1) * STG2;
#pragma unroll
        for (int ks = 0; ks < 2; ks++) {
            uint32_t ah[2][4], al[2][4];
#pragma unroll
            for (int mt = 0; mt < 2; mt++) {
                uint32_t row = (uint32_t)((wm + (mt << 4) + lr) * 128);
                ldsm4(ah[mt], base + SW(row + (ks << 5) + hb));
                ldsm4(al[mt], base + SW(row + 64 + (ks << 5) + hb));
            }
#pragma unroll
            for (int nt = 0; nt < 4; nt++) {
                uint32_t row = (uint32_t)((wn + (nt << 4) + lr) * 128);
                uint32_t bh[4], bl[4];
                ldsm4(bh, base + 16384u + SW(row + (ks << 5) + hb));
                ldsm4(bl, base + 16384u + SW(row + 64 + (ks << 5) + hb));
#pragma unroll
                for (int mt = 0; mt < 2; mt++) {
                    mma_bf16(ad[mt][nt * 2 + 0], ah[mt], bh[0], bh[2]);
                    mma_bf16(ad[mt][nt * 2 + 0], ah[mt], bl[0], bl[2]);
                    mma_bf16(ad[mt][nt * 2 + 0], al[mt], bh[0], bh[2]);
                    mma_bf16(ad[mt][nt * 2 + 1], ah[mt], bh[1], bh[3]);
                    mma_bf16(ad[mt][nt * 2 + 1], ah[mt], bl[1], bl[3]);
                    mma_bf16(ad[mt][nt * 2 + 1], al[mt], bh[1], bh[3]);
                }
            }
        }
        __syncthreads();
    }

#pragma unroll
    for (int mt = 0; mt < 2; mt++) {
        int r0 = rb + wm + (mt << 4) + (lane >> 2);
        float w0 = g_row_wt[r0], w1 = g_row_wt[r0 + 8];
#pragma unroll
        for (int nt = 0; nt < 8; nt++) {
            int c = col_base + wn + (nt << 3) + ((lane & 3) << 1);
            float2 o0 = make_float2(ad[mt][nt][0] * w0, ad[mt][nt][1] * w0);
            *(float2*)&g_Y[(size_t)r0 * DHID + c] = o0;
            float2 o1 = make_float2(ad[mt][nt][2] * w1, ad[mt][nt][3] * w1);
            *(float2*)&g_Y[(size_t)(r0 + 8) * DHID + c] = o1;
        }
    }
}

// ---------------- K6: combine ----------------
__global__ void __launch_bounds__(256) k_combine(float* __restrict__ out) {
    int t = blockIdx.x, tid = threadIdx.x;
    int d0 = tid << 2;
    float4 acc = make_float4(0.f, 0.f, 0.f, 0.f);
#pragma unroll
    for (int k = 0; k < 9; k++) {
        int r = g_token_rows[t * 9 + k];
        float4 v = *(const float4*)&g_Y[(size_t)r * DHID + d0];
        acc.x += v.x; acc.y += v.y; acc.z += v.z; acc.w += v.w;
    }
    *(float4*)&out[(size_t)t * DHID + d0] = acc;
}

// ---------------- launch ----------------
extern "C" void kernel_launch(void* const* d_in, const int* in_sizes, int n_in,
                              void* d_out, int out_size) {
    const float* x       = (const float*)d_in[0];
    const float* gate_w  = (const float*)d_in[1];
    const float* ebias   = (const float*)d_in[2];
    const float* w_gate  = (const float*)d_in[3];
    const float* w_up    = (const float*)d_in[4];
    const float* w_down  = (const float*)d_in[5];
    const float* sh_gate = (const float*)d_in[6];
    const float* sh_up   = (const float*)d_in[7];
    const float* sh_down = (const float*)d_in[8];
    float* out = (float*)d_out;

    cudaFuncSetAttribute(k_gemm1, cudaFuncAttributeMaxDynamicSharedMemorySize, SMEM1_BYTES);
    cudaFuncSetAttribute(k_gemm2, cudaFuncAttributeMaxDynamicSharedMemorySize, SMEM2_BYTES);

    __nv_bfloat16 *xh, *xl, *wgh, *wgl, *wuh, *wul, *wdh, *wdl;
    cudaGetSymbolAddress((void**)&xh, g_xh);  cudaGetSymbolAddress((void**)&xl, g_xl);
    cudaGetSymbolAddress((void**)&wgh, g_wgh); cudaGetSymbolAddress((void**)&wgl, g_wgl);
    cudaGetSymbolAddress((void**)&wuh, g_wuh); cudaGetSymbolAddress((void**)&wul, g_wul);
    cudaGetSymbolAddress((void**)&wdh, g_wdh); cudaGetSymbolAddress((void**)&wdl, g_wdl);

    const size_t SHOFF = (size_t)16 * WSZ;
    // block counts: elems/1024
    const int BX = 1024, BW = 16384, BS = 1024;
    SplitArgs sa;
    sa.src[0] = x;       sa.hi[0] = xh;          sa.lo[0] = xl;
    sa.src[1] = w_gate;  sa.hi[1] = wgh;         sa.lo[1] = wgl;
    sa.src[2] = sh_gate; sa.hi[2] = wgh + SHOFF; sa.lo[2] = wgl + SHOFF;
    sa.src[3] = w_up;    sa.hi[3] = wuh;         sa.lo[3] = wul;
    sa.src[4] = sh_up;   sa.hi[4] = wuh + SHOFF; sa.lo[4] = wul + SHOFF;
    sa.src[5] = w_down;  sa.hi[5] = wdh;         sa.lo[5] = wdl;
    sa.src[6] = sh_down; sa.hi[6] = wdh + SHOFF; sa.lo[6] = wdl + SHOFF;
    int acc = 0;
    const int bc[7] = {BX, BW, BS, BW, BS, BW, BS};
    for (int i = 0; i < 7; i++) { acc += bc[i]; sa.blk_end[i] = acc; }

    k_split_all<<<acc, 256>>>(sa);                         // launch 0
    k_init<<<(ROWS_CAP + 255) / 256, 256>>>();             // 1
    k_route<<<T_TOK, 128>>>(x, gate_w, ebias);             // 2
    k_offsets<<<1, 32>>>();                                // 3
    k_scatter<<<(T_TOK + 255) / 256, 256>>>();             // 4
    k_gemm1<<<dim3(ROW_TILES, NI / 64), 256, SMEM1_BYTES>>>();   // 5 <- ncu -s 5
    k_gemm2<<<dim3(ROW_TILES, DHID / 128), 256, SMEM2_BYTES>>>();
    k_combine<<<T_TOK, 256>>>(out);
}

// round 8
// speedup vs baseline: 3.0038x; 1.3085x over previous
#include <cuda_runtime.h>
#include <cuda_fp16.h>
#include <math.h>
#include <stdint.h>

#define T_TOK 1024
#define DHID 1024
#define NE 16
#define TOPK 8
#define NI 1024
#define ROUTE_SCALE 2.826f

#define ROW_TILES 88
#define ROWS_CAP (ROW_TILES * 128)
#define WSZ (1u << 20)

#define SW(o) ((o) ^ (((o) >> 3) & 0x70))

// ---------------- scratch ----------------
__device__ __half g_xh[T_TOK * DHID], g_xl[T_TOK * DHID];   // xl unused by GEMMs
__device__ __half g_wgh[17 * WSZ], g_wgl[17 * WSZ];
__device__ __half g_wuh[17 * WSZ], g_wul[17 * WSZ];
__device__ __half g_wdh[17 * WSZ], g_wdl[17 * WSZ];
__device__ __half g_Hh[(size_t)ROWS_CAP * NI];              // fp16 activations
__device__ float  g_Y[(size_t)ROWS_CAP * DHID];
__device__ int    g_row_token[ROWS_CAP];
__device__ float  g_row_wt[ROWS_CAP];
__device__ int    g_tile_expert[ROW_TILES];
__device__ int    g_token_rows[T_TOK * 9];
__device__ int    g_counts[NE + 1];
__device__ int    g_fill[NE + 1];
__device__ int    g_offsets[NE + 2];
__device__ int    g_topk_idx[T_TOK * TOPK];
__device__ float  g_topk_wt[T_TOK * TOPK];

// ---------------- helpers ----------------
__device__ __forceinline__ uint32_t smem_u32(const void* p) {
    uint32_t a;
    asm("{ .reg .u64 t; cvta.to.shared.u64 t, %1; cvt.u32.u64 %0, t; }" : "=r"(a) : "l"(p));
    return a;
}
__device__ __forceinline__ void ldsm4(uint32_t (&r)[4], uint32_t addr) {
    asm volatile("ldmatrix.sync.aligned.m8n8.x4.shared.b16 {%0,%1,%2,%3}, [%4];"
                 : "=r"(r[0]), "=r"(r[1]), "=r"(r[2]), "=r"(r[3]) : "r"(addr));
}
__device__ __forceinline__ void mma_f16(float (&d)[4], const uint32_t (&a)[4],
                                        uint32_t b0, uint32_t b1) {
    asm volatile("mma.sync.aligned.m16n8k16.row.col.f32.f16.f16.f32 "
                 "{%0,%1,%2,%3}, {%4,%5,%6,%7}, {%8,%9}, {%0,%1,%2,%3};"
                 : "+f"(d[0]), "+f"(d[1]), "+f"(d[2]), "+f"(d[3])
                 : "r"(a[0]), "r"(a[1]), "r"(a[2]), "r"(a[3]), "r"(b0), "r"(b1));
}
__device__ __forceinline__ void cpa16(uint32_t dst, const void* src) {
    asm volatile("cp.async.cg.shared.global [%0], [%1], 16;" :: "r"(dst), "l"(src));
}
#define CPA_COMMIT() asm volatile("cp.async.commit_group;" ::: "memory")
#define CPA_WAIT1()  asm volatile("cp.async.wait_group 1;" ::: "memory")
#define CPA_WAIT0()  asm volatile("cp.async.wait_group 0;" ::: "memory")

// ---------------- L0: merged fp32 -> fp16 hi/lo split + init --------------
struct SplitArgs {
    const float* src[7];
    __half* hi[7];
    __half* lo[7];
    int blk_end[7];
    int split_blocks;
};
__global__ void __launch_bounds__(256) k_split_all(SplitArgs a) {
    int b = blockIdx.x;
    if (b >= a.split_blocks) {   // init tail
        int i = (b - a.split_blocks) * 256 + threadIdx.x;
        if (i < ROWS_CAP) { g_row_token[i] = 0; g_row_wt[i] = 0.f; }
        if (i < ROW_TILES) g_tile_expert[i] = -1;
        if (i < NE + 1) { g_counts[i] = 0; g_fill[i] = 0; }
        return;
    }
    int s = 0;
    while (b >= a.blk_end[s]) s++;
    int base = s ? a.blk_end[s - 1] : 0;
    size_t i = ((size_t)(b - base) * 256 + threadIdx.x) << 2;
    float4 v = *(const float4*)(a.src[s] + i);
    __half h0 = __float2half(v.x), h1 = __float2half(v.y);
    __half h2 = __float2half(v.z), h3 = __float2half(v.w);
    uint2 hp;
    hp.x = (uint32_t)__half_as_ushort(h0) | ((uint32_t)__half_as_ushort(h1) << 16);
    hp.y = (uint32_t)__half_as_ushort(h2) | ((uint32_t)__half_as_ushort(h3) << 16);
    *(uint2*)&a.hi[s][i] = hp;
    __half l0 = __float2half(v.x - __half2float(h0));
    __half l1 = __float2half(v.y - __half2float(h1));
    __half l2 = __float2half(v.z - __half2float(h2));
    __half l3 = __float2half(v.w - __half2float(h3));
    uint2 lp;
    lp.x = (uint32_t)__half_as_ushort(l0) | ((uint32_t)__half_as_ushort(l1) << 16);
    lp.y = (uint32_t)__half_as_ushort(l2) | ((uint32_t)__half_as_ushort(l3) << 16);
    *(uint2*)&a.lo[s][i] = lp;
}

// ---------------- L1: routing ----------------
__global__ void __launch_bounds__(128) k_route(const float* __restrict__ x,
                                               const float* __restrict__ gw,
                                               const float* __restrict__ bias) {
    __shared__ float xs[DHID];
    __shared__ float gates[NE];
    int t = blockIdx.x, tid = threadIdx.x;
    for (int i = tid; i < DHID; i += 128) xs[i] = x[(size_t)t * DHID + i];
    __syncthreads();
    int e = tid >> 3, p = tid & 7;
    const float* w = gw + e * DHID + p * 128;
    const float* xv = xs + p * 128;
    float s = 0.f;
#pragma unroll 8
    for (int d = 0; d < 128; d++) s += xv[d] * w[d];
    s += __shfl_down_sync(0xffffffffu, s, 4, 8);
    s += __shfl_down_sync(0xffffffffu, s, 2, 8);
    s += __shfl_down_sync(0xffffffffu, s, 1, 8);
    if (p == 0) gates[e] = s;
    __syncthreads();
    if (tid == 0) {
        float sc[NE], sel[NE];
        bool used[NE];
        for (int i = 0; i < NE; i++) {
            sc[i] = 1.f / (1.f + expf(-gates[i]));
            sel[i] = sc[i] + bias[i];
            used[i] = false;
        }
        int idx[TOPK]; float wv[TOPK]; float sum = 0.f;
        for (int k = 0; k < TOPK; k++) {
            int best = -1; float bv = -1e30f;
            for (int i = 0; i < NE; i++)
                if (!used[i] && sel[i] > bv) { bv = sel[i]; best = i; }
            used[best] = true; idx[k] = best; wv[k] = sc[best]; sum += sc[best];
        }
        float inv = ROUTE_SCALE / sum;
        for (int k = 0; k < TOPK; k++) {
            g_topk_idx[t * TOPK + k] = idx[k];
            g_topk_wt[t * TOPK + k] = wv[k] * inv;
            atomicAdd(&g_counts[idx[k]], 1);
        }
    }
}

// ---------------- L2: offsets + scatter (single block) ----------------
__global__ void __launch_bounds__(256) k_offsets_scatter() {
    int tid = threadIdx.x;
    if (tid == 0) {
        g_counts[NE] = T_TOK;
        int off = 0;
        for (int e = 0; e <= NE; e++) {
            g_offsets[e] = off;
            int tiles = (g_counts[e] + 127) >> 7;
            for (int j = 0; j < tiles; j++) g_tile_expert[(off >> 7) + j] = e;
            off += tiles << 7;
        }
        g_offsets[NE + 1] = off;
    }
    __syncthreads();
    for (int t = tid; t < T_TOK; t += 256) {
        for (int k = 0; k < TOPK; k++) {
            int e = g_topk_idx[t * TOPK + k];
            int pos = atomicAdd(&g_fill[e], 1);
            int r = g_offsets[e] + pos;
            g_row_token[r] = t;
            g_row_wt[r] = g_topk_wt[t * TOPK + k];
            g_token_rows[t * 9 + k] = r;
        }
        int r = g_offsets[NE] + t;
        g_row_token[r] = t;
        g_row_wt[r] = 1.f;
        g_token_rows[t * 9 + 8] = r;
    }
}

// ---------------- L3: gemm1 (A=fp16 hi, B=hi+lo; 2-term) ------------------
// Stage 48KB: A 0..16K (128x128B), Gh 16K..24K, Gl 24K..32K, Uh 32K..40K, Ul 40K..48K
#define STG1 49152u
#define SMEM1_BYTES (2 * STG1)
__global__ void __launch_bounds__(256, 1) k_gemm1() {
    extern __shared__ char smem[];
    int e = g_tile_expert[blockIdx.x];
    if (e < 0) return;
    const __half* wgh = g_wgh + ((size_t)e << 20);
    const __half* wgl = g_wgl + ((size_t)e << 20);
    const __half* wuh = g_wuh + ((size_t)e << 20);
    const __half* wul = g_wul + ((size_t)e << 20);

    const int tid = threadIdx.x, wid = tid >> 5, lane = tid & 31;
    const int wm = (wid >> 1) << 5;
    const int wn = (wid & 1) << 5;
    const uint32_t sb = smem_u32(smem);
    const int col_base = blockIdx.y << 6;
    const int rb = blockIdx.x << 7;

    const int crow = tid >> 3;
    const int cc8 = tid & 7;
    int tok4[4];
#pragma unroll
    for (int i = 0; i < 4; i++) tok4[i] = g_row_token[rb + crow + (i << 5)];

    auto issue = [&](int stg, int k0) {
        uint32_t base = sb + (uint32_t)stg * STG1;
#pragma unroll
        for (int i = 0; i < 4; i++) {
            int r = crow + (i << 5);
            uint32_t boff = SW((uint32_t)(r * 128 + cc8 * 16));
            cpa16(base + boff, g_xh + (size_t)tok4[i] * DHID + k0 + cc8 * 8);
        }
#pragma unroll
        for (int i = 0; i < 2; i++) {
            int r = crow + (i << 5);
            uint32_t boff = SW((uint32_t)(r * 128 + cc8 * 16));
            size_t go = (size_t)(col_base + r) * DHID + k0 + cc8 * 8;
            cpa16(base + 16384u + boff, wgh + go);
            cpa16(base + 24576u + boff, wgl + go);
            cpa16(base + 32768u + boff, wuh + go);
            cpa16(base + 40960u + boff, wul + go);
        }
        CPA_COMMIT();
    };

    float ag[2][4][4] = {}, au[2][4][4] = {};
    const int lr = lane & 15;
    const int hb = (lane >> 4) << 4;

    issue(0, 0);
    const int NK = DHID / 64;
    for (int kc = 0; kc < NK; kc++) {
        if (kc + 1 < NK) issue((kc + 1) & 1, (kc + 1) << 6);
        if (kc + 1 < NK) { CPA_WAIT1(); } else { CPA_WAIT0(); }
        __syncthreads();
        uint32_t base = sb + (uint32_t)(kc & 1) * STG1;
#pragma unroll
        for (int ks = 0; ks < 4; ks++) {
            uint32_t ah[2][4];
#pragma unroll
            for (int mt = 0; mt < 2; mt++) {
                uint32_t off = SW((uint32_t)((wm + (mt << 4) + lr) * 128 + (ks << 5) + hb));
                ldsm4(ah[mt], base + off);
            }
#pragma unroll
            for (int nt = 0; nt < 2; nt++) {
                uint32_t off = SW((uint32_t)((wn + (nt << 4) + lr) * 128 + (ks << 5) + hb));
                uint32_t gh[4], gl[4], uh[4], ul[4];
                ldsm4(gh, base + 16384u + off);
                ldsm4(gl, base + 24576u + off);
                ldsm4(uh, base + 32768u + off);
                ldsm4(ul, base + 40960u + off);
#pragma unroll
                for (int mt = 0; mt < 2; mt++) {
                    mma_f16(ag[mt][nt * 2 + 0], ah[mt], gh[0], gh[2]);
                    mma_f16(ag[mt][nt * 2 + 0], ah[mt], gl[0], gl[2]);
                    mma_f16(ag[mt][nt * 2 + 1], ah[mt], gh[1], gh[3]);
                    mma_f16(ag[mt][nt * 2 + 1], ah[mt], gl[1], gl[3]);
                    mma_f16(au[mt][nt * 2 + 0], ah[mt], uh[0], uh[2]);
                    mma_f16(au[mt][nt * 2 + 0], ah[mt], ul[0], ul[2]);
                    mma_f16(au[mt][nt * 2 + 1], ah[mt], uh[1], uh[3]);
                    mma_f16(au[mt][nt * 2 + 1], ah[mt], ul[1], ul[3]);
                }
            }
        }
        __syncthreads();
    }

    // epilogue: SwiGLU -> fp16 H
#pragma unroll
    for (int mt = 0; mt < 2; mt++) {
        int r0 = rb + wm + (mt << 4) + (lane >> 2);
#pragma unroll
        for (int nt = 0; nt < 4; nt++) {
            int c = col_base + wn + (nt << 3) + ((lane & 3) << 1);
#pragma unroll
            for (int half_i = 0; half_i < 2; half_i++) {
                int r = r0 + half_i * 8;
                float g0 = ag[mt][nt][half_i * 2 + 0], g1 = ag[mt][nt][half_i * 2 + 1];
                float u0 = au[mt][nt][half_i * 2 + 0], u1 = au[mt][nt][half_i * 2 + 1];
                float h0 = g0 * u0 / (1.f + __expf(-g0));
                float h1 = g1 * u1 / (1.f + __expf(-g1));
                __half2 hp = __floats2half2_rn(h0, h1);
                *(__half2*)&g_Hh[(size_t)r * NI + c] = hp;
            }
        }
    }
}

// ---------------- L4: gemm2 (A=H fp16, B=hi+lo; 2-term) -------------------
// Stage 48KB: A 0..16K, Bh 16K..32K, Bl 32K..48K
#define STG2 49152u
#define SMEM2_BYTES (2 * STG2)
__global__ void __launch_bounds__(256, 1) k_gemm2() {
    extern __shared__ char smem[];
    int e = g_tile_expert[blockIdx.x];
    if (e < 0) return;
    const __half* wdh = g_wdh + ((size_t)e << 20);
    const __half* wdl = g_wdl + ((size_t)e << 20);

    const int tid = threadIdx.x, wid = tid >> 5, lane = tid & 31;
    const int wm = (wid >> 1) << 5;
    const int wn = (wid & 1) << 6;
    const uint32_t sb = smem_u32(smem);
    const int col_base = blockIdx.y << 7;
    const int rb = blockIdx.x << 7;

    const int crow = tid >> 3;
    const int cc8 = tid & 7;

    auto issue = [&](int stg, int k0) {
        uint32_t base = sb + (uint32_t)stg * STG2;
#pragma unroll
        for (int i = 0; i < 4; i++) {
            int r = crow + (i << 5);
            uint32_t boff = SW((uint32_t)(r * 128 + cc8 * 16));
            cpa16(base + boff, g_Hh + (size_t)(rb + r) * NI + k0 + cc8 * 8);
            size_t go = (size_t)(col_base + r) * NI + k0 + cc8 * 8;
            cpa16(base + 16384u + boff, wdh + go);
            cpa16(base + 32768u + boff, wdl + go);
        }
        CPA_COMMIT();
    };

    float ad[2][8][4] = {};
    const int lr = lane & 15;
    const int hb = (lane >> 4) << 4;

    issue(0, 0);
    const int NK = NI / 64;
    for (int kc = 0; kc < NK; kc++) {
        if (kc + 1 < NK) issue((kc + 1) & 1, (kc + 1) << 6);
        if (kc + 1 < NK) { CPA_WAIT1(); } else { CPA_WAIT0(); }
        __syncthreads();
        uint32_t base = sb + (uint32_t)(kc & 1) * STG2;
#pragma unroll
        for (int ks = 0; ks < 4; ks++) {
            uint32_t ah[2][4];
#pragma unroll
            for (int mt = 0; mt < 2; mt++) {
                uint32_t off = SW((uint32_t)((wm + (mt << 4) + lr) * 128 + (ks << 5) + hb));
                ldsm4(ah[mt], base + off);
            }
#pragma unroll
            for (int nt = 0; nt < 4; nt++) {
                uint32_t off = SW((uint32_t)((wn + (nt << 4) + lr) * 128 + (ks << 5) + hb));
                uint32_t bh[4], bl[4];
                ldsm4(bh, base + 16384u + off);
                ldsm4(bl, base + 32768u + off);
#pragma unroll
                for (int mt = 0; mt < 2; mt++) {
                    mma_f16(ad[mt][nt * 2 + 0], ah[mt], bh[0], bh[2]);
                    mma_f16(ad[mt][nt * 2 + 0], ah[mt], bl[0], bl[2]);
                    mma_f16(ad[mt][nt * 2 + 1], ah[mt], bh[1], bh[3]);
                    mma_f16(ad[mt][nt * 2 + 1], ah[mt], bl[1], bl[3]);
                }
            }
        }
        __syncthreads();
    }

#pragma unroll
    for (int mt = 0; mt < 2; mt++) {
        int r0 = rb + wm + (mt << 4) + (lane >> 2);
        float w0 = g_row_wt[r0], w1 = g_row_wt[r0 + 8];
#pragma unroll
        for (int nt = 0; nt < 8; nt++) {
            int c = col_base + wn + (nt << 3) + ((lane & 3) << 1);
            float2 o0 = make_float2(ad[mt][nt][0] * w0, ad[mt][nt][1] * w0);
            *(float2*)&g_Y[(size_t)r0 * DHID + c] = o0;
            float2 o1 = make_float2(ad[mt][nt][2] * w1, ad[mt][nt][3] * w1);
            *(float2*)&g_Y[(size_t)(r0 + 8) * DHID + c] = o1;
        }
    }
}

// ---------------- L5: combine ----------------
__global__ void __launch_bounds__(256) k_combine(float* __restrict__ out) {
    int t = blockIdx.x, tid = threadIdx.x;
    int d0 = tid << 2;
    float4 acc = make_float4(0.f, 0.f, 0.f, 0.f);
#pragma unroll
    for (int k = 0; k < 9; k++) {
        int r = g_token_rows[t * 9 + k];
        float4 v = *(const float4*)&g_Y[(size_t)r * DHID + d0];
        acc.x += v.x; acc.y += v.y; acc.z += v.z; acc.w += v.w;
    }
    *(float4*)&out[(size_t)t * DHID + d0] = acc;
}

// ---------------- launch ----------------
extern "C" void kernel_launch(void* const* d_in, const int* in_sizes, int n_in,
                              void* d_out, int out_size) {
    const float* x       = (const float*)d_in[0];
    const float* gate_w  = (const float*)d_in[1];
    const float* ebias   = (const float*)d_in[2];
    const float* w_gate  = (const float*)d_in[3];
    const float* w_up    = (const float*)d_in[4];
    const float* w_down  = (const float*)d_in[5];
    const float* sh_gate = (const float*)d_in[6];
    const float* sh_up   = (const float*)d_in[7];
    const float* sh_down = (const float*)d_in[8];
    float* out = (float*)d_out;

    cudaFuncSetAttribute(k_gemm1, cudaFuncAttributeMaxDynamicSharedMemorySize, SMEM1_BYTES);
    cudaFuncSetAttribute(k_gemm2, cudaFuncAttributeMaxDynamicSharedMemorySize, SMEM2_BYTES);

    __half *xh, *xl, *wgh, *wgl, *wuh, *wul, *wdh, *wdl;
    cudaGetSymbolAddress((void**)&xh, g_xh);  cudaGetSymbolAddress((void**)&xl, g_xl);
    cudaGetSymbolAddress((void**)&wgh, g_wgh); cudaGetSymbolAddress((void**)&wgl, g_wgl);
    cudaGetSymbolAddress((void**)&wuh, g_wuh); cudaGetSymbolAddress((void**)&wul, g_wul);
    cudaGetSymbolAddress((void**)&wdh, g_wdh); cudaGetSymbolAddress((void**)&wdl, g_wdl);

    const size_t SHOFF = (size_t)16 * WSZ;
    const int BX = 1024, BW = 16384, BS = 1024;
    SplitArgs sa;
    sa.src[0] = x;       sa.hi[0] = xh;          sa.lo[0] = xl;
    sa.src[1] = w_gate;  sa.hi[1] = wgh;         sa.lo[1] = wgl;
    sa.src[2] = sh_gate; sa.hi[2] = wgh + SHOFF; sa.lo[2] = wgl + SHOFF;
    sa.src[3] = w_up;    sa.hi[3] = wuh;         sa.lo[3] = wul;
    sa.src[4] = sh_up;   sa.hi[4] = wuh + SHOFF; sa.lo[4] = wul + SHOFF;
    sa.src[5] = w_down;  sa.hi[5] = wdh;         sa.lo[5] = wdl;
    sa.src[6] = sh_down; sa.hi[6] = wdh + SHOFF; sa.lo[6] = wdl + SHOFF;
    int acc = 0;
    const int bc[7] = {BX, BW, BS, BW, BS, BW, BS};
    for (int i = 0; i < 7; i++) { acc += bc[i]; sa.blk_end[i] = acc; }
    sa.split_blocks = acc;
    int init_blocks = (ROWS_CAP + 255) / 256;

    k_split_all<<<acc + init_blocks, 256>>>(sa);                  // idx 0 (split + init)
    k_route<<<T_TOK, 128>>>(x, gate_w, ebias);                    // idx 1
    k_offsets_scatter<<<1, 256>>>();                              // idx 2
    k_gemm1<<<dim3(ROW_TILES, NI / 64), 256, SMEM1_BYTES>>>();    // idx 3 <- ncu capture
    k_gemm2<<<dim3(ROW_TILES, DHID / 128), 256, SMEM2_BYTES>>>(); // idx 4
    k_combine<<<T_TOK, 256>>>(out);                               // idx 5
}

// round 9
// speedup vs baseline: 3.0453x; 1.0138x over previous
#include <cuda_runtime.h>
#include <cuda_fp16.h>
#include <math.h>
#include <stdint.h>

#define T_TOK 1024
#define DHID 1024
#define NE 16
#define TOPK 8
#define NI 1024
#define ROUTE_SCALE 2.826f

#define ROW_TILES 88
#define ROWS_CAP (ROW_TILES * 128)
#define WSZ (1u << 20)

#define SW(o) ((o) ^ (((o) >> 3) & 0x70))

// ---------------- scratch ----------------
__device__ __half g_xh[T_TOK * DHID], g_xl[T_TOK * DHID];
__device__ __half g_wgh[17 * WSZ], g_wgl[17 * WSZ];
__device__ __half g_wuh[17 * WSZ], g_wul[17 * WSZ];
__device__ __half g_wdh[17 * WSZ], g_wdl[17 * WSZ];
__device__ __half g_Hh[(size_t)ROWS_CAP * NI];
__device__ float  g_Y[(size_t)ROWS_CAP * DHID];
__device__ int    g_row_token[ROWS_CAP];
__device__ float  g_row_wt[ROWS_CAP];
__device__ int    g_tile_expert[ROW_TILES];
__device__ int    g_token_rows[T_TOK * 9];
__device__ int    g_counts[NE + 1];
__device__ int    g_fill[NE + 1];
__device__ int    g_offsets[NE + 2];
__device__ int    g_topk_idx[T_TOK * TOPK];
__device__ float  g_topk_wt[T_TOK * TOPK];

// ---------------- helpers ----------------
__device__ __forceinline__ uint32_t smem_u32(const void* p) {
    uint32_t a;
    asm("{ .reg .u64 t; cvta.to.shared.u64 t, %1; cvt.u32.u64 %0, t; }" : "=r"(a) : "l"(p));
    return a;
}
__device__ __forceinline__ void ldsm4(uint32_t (&r)[4], uint32_t addr) {
    asm volatile("ldmatrix.sync.aligned.m8n8.x4.shared.b16 {%0,%1,%2,%3}, [%4];"
                 : "=r"(r[0]), "=r"(r[1]), "=r"(r[2]), "=r"(r[3]) : "r"(addr));
}
__device__ __forceinline__ void mma_f16(float (&d)[4], const uint32_t (&a)[4],
                                        uint32_t b0, uint32_t b1) {
    asm volatile("mma.sync.aligned.m16n8k16.row.col.f32.f16.f16.f32 "
                 "{%0,%1,%2,%3}, {%4,%5,%6,%7}, {%8,%9}, {%0,%1,%2,%3};"
                 : "+f"(d[0]), "+f"(d[1]), "+f"(d[2]), "+f"(d[3])
                 : "r"(a[0]), "r"(a[1]), "r"(a[2]), "r"(a[3]), "r"(b0), "r"(b1));
}
__device__ __forceinline__ void cpa16(uint32_t dst, const void* src) {
    asm volatile("cp.async.cg.shared.global [%0], [%1], 16;" :: "r"(dst), "l"(src));
}
#define CPA_COMMIT() asm volatile("cp.async.commit_group;" ::: "memory")
#define CPA_WAIT1()  asm volatile("cp.async.wait_group 1;" ::: "memory")
#define CPA_WAIT0()  asm volatile("cp.async.wait_group 0;" ::: "memory")

// ---------------- L0: split + init ----------------
struct SplitArgs {
    const float* src[7];
    __half* hi[7];
    __half* lo[7];
    int blk_end[7];
    int split_blocks;
};
__global__ void __launch_bounds__(256) k_split_all(SplitArgs a) {
    int b = blockIdx.x;
    if (b >= a.split_blocks) {
        int i = (b - a.split_blocks) * 256 + threadIdx.x;
        if (i < ROWS_CAP) { g_row_token[i] = 0; g_row_wt[i] = 0.f; }
        if (i < ROW_TILES) g_tile_expert[i] = -1;
        if (i < NE + 1) { g_counts[i] = 0; g_fill[i] = 0; }
        return;
    }
    int s = 0;
    while (b >= a.blk_end[s]) s++;
    int base = s ? a.blk_end[s - 1] : 0;
    size_t i = ((size_t)(b - base) * 256 + threadIdx.x) << 2;
    float4 v = *(const float4*)(a.src[s] + i);
    __half h0 = __float2half(v.x), h1 = __float2half(v.y);
    __half h2 = __float2half(v.z), h3 = __float2half(v.w);
    uint2 hp;
    hp.x = (uint32_t)__half_as_ushort(h0) | ((uint32_t)__half_as_ushort(h1) << 16);
    hp.y = (uint32_t)__half_as_ushort(h2) | ((uint32_t)__half_as_ushort(h3) << 16);
    *(uint2*)&a.hi[s][i] = hp;
    __half l0 = __float2half(v.x - __half2float(h0));
    __half l1 = __float2half(v.y - __half2float(h1));
    __half l2 = __float2half(v.z - __half2float(h2));
    __half l3 = __float2half(v.w - __half2float(h3));
    uint2 lp;
    lp.x = (uint32_t)__half_as_ushort(l0) | ((uint32_t)__half_as_ushort(l1) << 16);
    lp.y = (uint32_t)__half_as_ushort(l2) | ((uint32_t)__half_as_ushort(l3) << 16);
    *(uint2*)&a.lo[s][i] = lp;
}

// ---------------- L1: routing ----------------
__global__ void __launch_bounds__(128) k_route(const float* __restrict__ x,
                                               const float* __restrict__ gw,
                                               const float* __restrict__ bias) {
    __shared__ float xs[DHID];
    __shared__ float gates[NE];
    int t = blockIdx.x, tid = threadIdx.x;
    for (int i = tid; i < DHID; i += 128) xs[i] = x[(size_t)t * DHID + i];
    __syncthreads();
    int e = tid >> 3, p = tid & 7;
    const float* w = gw + e * DHID + p * 128;
    const float* xv = xs + p * 128;
    float s = 0.f;
#pragma unroll 8
    for (int d = 0; d < 128; d++) s += xv[d] * w[d];
    s += __shfl_down_sync(0xffffffffu, s, 4, 8);
    s += __shfl_down_sync(0xffffffffu, s, 2, 8);
    s += __shfl_down_sync(0xffffffffu, s, 1, 8);
    if (p == 0) gates[e] = s;
    __syncthreads();
    if (tid == 0) {
        float sc[NE], sel[NE];
        bool used[NE];
        for (int i = 0; i < NE; i++) {
            sc[i] = 1.f / (1.f + expf(-gates[i]));
            sel[i] = sc[i] + bias[i];
            used[i] = false;
        }
        int idx[TOPK]; float wv[TOPK]; float sum = 0.f;
        for (int k = 0; k < TOPK; k++) {
            int best = -1; float bv = -1e30f;
            for (int i = 0; i < NE; i++)
                if (!used[i] && sel[i] > bv) { bv = sel[i]; best = i; }
            used[best] = true; idx[k] = best; wv[k] = sc[best]; sum += sc[best];
        }
        float inv = ROUTE_SCALE / sum;
        for (int k = 0; k < TOPK; k++) {
            g_topk_idx[t * TOPK + k] = idx[k];
            g_topk_wt[t * TOPK + k] = wv[k] * inv;
            atomicAdd(&g_counts[idx[k]], 1);
        }
    }
}

// ---------------- L2: offsets + scatter ----------------
__global__ void __launch_bounds__(256) k_offsets_scatter() {
    int tid = threadIdx.x;
    if (tid == 0) {
        g_counts[NE] = T_TOK;
        int off = 0;
        for (int e = 0; e <= NE; e++) {
            g_offsets[e] = off;
            int tiles = (g_counts[e] + 127) >> 7;
            for (int j = 0; j < tiles; j++) g_tile_expert[(off >> 7) + j] = e;
            off += tiles << 7;
        }
        g_offsets[NE + 1] = off;
    }
    __syncthreads();
    for (int t = tid; t < T_TOK; t += 256) {
        for (int k = 0; k < TOPK; k++) {
            int e = g_topk_idx[t * TOPK + k];
            int pos = atomicAdd(&g_fill[e], 1);
            int r = g_offsets[e] + pos;
            g_row_token[r] = t;
            g_row_wt[r] = g_topk_wt[t * TOPK + k];
            g_token_rows[t * 9 + k] = r;
        }
        int r = g_offsets[NE] + t;
        g_row_token[r] = t;
        g_row_wt[r] = 1.f;
        g_token_rows[t * 9 + 8] = r;
    }
}

// ---------------- L3: gemm1 (512 thr, 3-stage, 1 bar/iter) ----------------
// Stage 48KB: A 0..16K (128x128B), GH 16K, GL 24K, UH 32K, UL 40K
#define STG1 49152u
#define SMEM1_BYTES (3 * STG1)
__global__ void __launch_bounds__(512, 1) k_gemm1() {
    extern __shared__ char smem[];
    int e = g_tile_expert[blockIdx.x];
    if (e < 0) return;

    const int tid = threadIdx.x, wid = tid >> 5, lane = tid & 31;
    const int wm = (wid & 3) << 5;          // m tile base (0..96)
    const int wn = (wid >> 2) << 4;         // n tile base (0,16,32,48)
    const uint32_t sb = smem_u32(smem);
    const int col_base = blockIdx.y << 6;
    const int rb = blockIdx.x << 7;

    // ---- load assignment: row r=tid>>3 (A rows r, r+64; W row r), chunk tid&7
    const int r = tid >> 3;
    const int c8 = (tid & 7) << 3;           // halfword elem offset 0..56
    const uint32_t dA = SW((uint32_t)(r * 128 + (c8 << 1)));
    const __half* pA0 = g_xh + (size_t)g_row_token[rb + r] * DHID + c8;
    const __half* pA1 = g_xh + (size_t)g_row_token[rb + r + 64] * DHID + c8;
    const size_t wbase = ((size_t)e << 20) + (size_t)(col_base + r) * DHID + c8;
    const __half* pGh = g_wgh + wbase;
    const __half* pGl = g_wgl + wbase;
    const __half* pUh = g_wuh + wbase;
    const __half* pUl = g_wul + wbase;

    int kadv = 0;
    auto issue = [&](int stg) {
        uint32_t base = sb + (uint32_t)stg * STG1;
        cpa16(base + dA, pA0 + kadv);
        cpa16(base + 8192u + dA, pA1 + kadv);
        cpa16(base + 16384u + dA, pGh + kadv);
        cpa16(base + 24576u + dA, pGl + kadv);
        cpa16(base + 32768u + dA, pUh + kadv);
        cpa16(base + 40960u + dA, pUl + kadv);
        CPA_COMMIT();
        kadv += 64;
    };

    // ---- ldsm addressing
    const int lr = lane & 15;
    const uint32_t hb = (uint32_t)((lane >> 4) << 4);
    uint32_t arow[2], amask[2];
#pragma unroll
    for (int mt = 0; mt < 2; mt++) {
        int rr = wm + (mt << 4) + lr;
        arow[mt] = (uint32_t)(rr * 128);
        amask[mt] = (uint32_t)((rr & 7) << 4);
    }
    const int brr = wn + lr;
    const uint32_t brow = (uint32_t)(brr * 128);
    const uint32_t bmask = (uint32_t)((brr & 7) << 4);

    float ag[2][2][4] = {}, au[2][2][4] = {};

    issue(0); issue(1);
    const int NK = DHID / 64;
    int stg = 2;
    for (int kc = 0; kc < NK; kc++) {
        if (kc + 1 == NK) { CPA_WAIT0(); } else { CPA_WAIT1(); }
        __syncthreads();
        if (kc + 2 < NK) { issue(stg); stg = (stg == 2) ? 0 : stg + 1; }
        uint32_t base = sb + (uint32_t)((kc % 3)) * STG1;
#pragma unroll
        for (int ks = 0; ks < 4; ks++) {
            uint32_t kb = (uint32_t)(ks << 5) | hb;
            uint32_t ah[2][4];
#pragma unroll
            for (int mt = 0; mt < 2; mt++)
                ldsm4(ah[mt], base + arow[mt] + (kb ^ amask[mt]));
            uint32_t boff = brow + (kb ^ bmask);
            uint32_t gh[4], gl[4], uh[4], ul[4];
            ldsm4(gh, base + 16384u + boff);
            ldsm4(gl, base + 24576u + boff);
            ldsm4(uh, base + 32768u + boff);
            ldsm4(ul, base + 40960u + boff);
#pragma unroll
            for (int mt = 0; mt < 2; mt++) {
                mma_f16(ag[mt][0], ah[mt], gh[0], gh[2]);
                mma_f16(ag[mt][0], ah[mt], gl[0], gl[2]);
                mma_f16(ag[mt][1], ah[mt], gh[1], gh[3]);
                mma_f16(ag[mt][1], ah[mt], gl[1], gl[3]);
                mma_f16(au[mt][0], ah[mt], uh[0], uh[2]);
                mma_f16(au[mt][0], ah[mt], ul[0], ul[2]);
                mma_f16(au[mt][1], ah[mt], uh[1], uh[3]);
                mma_f16(au[mt][1], ah[mt], ul[1], ul[3]);
            }
        }
    }

    // epilogue: SwiGLU -> fp16 H
#pragma unroll
    for (int mt = 0; mt < 2; mt++) {
        int r0 = rb + wm + (mt << 4) + (lane >> 2);
#pragma unroll
        for (int n8 = 0; n8 < 2; n8++) {
            int c = col_base + wn + (n8 << 3) + ((lane & 3) << 1);
#pragma unroll
            for (int hf = 0; hf < 2; hf++) {
                int rr = r0 + hf * 8;
                float g0 = ag[mt][n8][hf * 2 + 0], g1 = ag[mt][n8][hf * 2 + 1];
                float u0 = au[mt][n8][hf * 2 + 0], u1 = au[mt][n8][hf * 2 + 1];
                float h0 = g0 * u0 / (1.f + __expf(-g0));
                float h1 = g1 * u1 / (1.f + __expf(-g1));
                *(__half2*)&g_Hh[(size_t)rr * NI + c] = __floats2half2_rn(h0, h1);
            }
        }
    }
}

// ---------------- L4: gemm2 (512 thr, 3-stage, 1 bar/iter) ----------------
// Stage 48KB: A 0..16K, BH 16K..32K, BL 32K..48K
#define STG2 49152u
#define SMEM2_BYTES (3 * STG2)
__global__ void __launch_bounds__(512, 1) k_gemm2() {
    extern __shared__ char smem[];
    int e = g_tile_expert[blockIdx.x];
    if (e < 0) return;

    const int tid = threadIdx.x, wid = tid >> 5, lane = tid & 31;
    const int wm = (wid & 3) << 5;
    const int wn = (wid >> 2) << 5;         // 0,32,64,96
    const uint32_t sb = smem_u32(smem);
    const int col_base = blockIdx.y << 7;
    const int rb = blockIdx.x << 7;

    const int r = tid >> 3;
    const int c8 = (tid & 7) << 3;
    const uint32_t dA = SW((uint32_t)(r * 128 + (c8 << 1)));
    const __half* pA0 = g_Hh + (size_t)(rb + r) * NI + c8;
    const __half* pA1 = g_Hh + (size_t)(rb + r + 64) * NI + c8;
    const size_t wb0 = ((size_t)e << 20) + (size_t)(col_base + r) * NI + c8;
    const size_t wb1 = ((size_t)e << 20) + (size_t)(col_base + r + 64) * NI + c8;
    const __half* pBh0 = g_wdh + wb0;
    const __half* pBh1 = g_wdh + wb1;
    const __half* pBl0 = g_wdl + wb0;
    const __half* pBl1 = g_wdl + wb1;

    int kadv = 0;
    auto issue = [&](int stg) {
        uint32_t base = sb + (uint32_t)stg * STG2;
        cpa16(base + dA, pA0 + kadv);
        cpa16(base + 8192u + dA, pA1 + kadv);
        cpa16(base + 16384u + dA, pBh0 + kadv);
        cpa16(base + 24576u + dA, pBh1 + kadv);
        cpa16(base + 32768u + dA, pBl0 + kadv);
        cpa16(base + 40960u + dA, pBl1 + kadv);
        CPA_COMMIT();
        kadv += 64;
    };

    const int lr = lane & 15;
    const uint32_t hb = (uint32_t)((lane >> 4) << 4);
    uint32_t arow[2], amask[2];
#pragma unroll
    for (int mt = 0; mt < 2; mt++) {
        int rr = wm + (mt << 4) + lr;
        arow[mt] = (uint32_t)(rr * 128);
        amask[mt] = (uint32_t)((rr & 7) << 4);
    }
    uint32_t brow[2], bmask[2];
#pragma unroll
    for (int nt = 0; nt < 2; nt++) {
        int rr = wn + (nt << 4) + lr;
        brow[nt] = (uint32_t)(rr * 128);
        bmask[nt] = (uint32_t)((rr & 7) << 4);
    }

    float ad[2][4][4] = {};

    issue(0); issue(1);
    const int NK = NI / 64;
    int stg = 2;
    for (int kc = 0; kc < NK; kc++) {
        if (kc + 1 == NK) { CPA_WAIT0(); } else { CPA_WAIT1(); }
        __syncthreads();
        if (kc + 2 < NK) { issue(stg); stg = (stg == 2) ? 0 : stg + 1; }
        uint32_t base = sb + (uint32_t)((kc % 3)) * STG2;
#pragma unroll
        for (int ks = 0; ks < 4; ks++) {
            uint32_t kb = (uint32_t)(ks << 5) | hb;
            uint32_t ah[2][4];
#pragma unroll
            for (int mt = 0; mt < 2; mt++)
                ldsm4(ah[mt], base + arow[mt] + (kb ^ amask[mt]));
#pragma unroll
            for (int nt = 0; nt < 2; nt++) {
                uint32_t boff = brow[nt] + (kb ^ bmask[nt]);
                uint32_t bh[4], bl[4];
                ldsm4(bh, base + 16384u + boff);
                ldsm4(bl, base + 32768u + boff);
#pragma unroll
                for (int mt = 0; mt < 2; mt++) {
                    mma_f16(ad[mt][nt * 2 + 0], ah[mt], bh[0], bh[2]);
                    mma_f16(ad[mt][nt * 2 + 0], ah[mt], bl[0], bl[2]);
                    mma_f16(ad[mt][nt * 2 + 1], ah[mt], bh[1], bh[3]);
                    mma_f16(ad[mt][nt * 2 + 1], ah[mt], bl[1], bl[3]);
                }
            }
        }
    }

#pragma unroll
    for (int mt = 0; mt < 2; mt++) {
        int r0 = rb + wm + (mt << 4) + (lane >> 2);
        float w0 = g_row_wt[r0], w1 = g_row_wt[r0 + 8];
#pragma unroll
        for (int n8 = 0; n8 < 4; n8++) {
            int c = col_base + wn + (n8 << 3) + ((lane & 3) << 1);
            float2 o0 = make_float2(ad[mt][n8][0] * w0, ad[mt][n8][1] * w0);
            *(float2*)&g_Y[(size_t)r0 * DHID + c] = o0;
            float2 o1 = make_float2(ad[mt][n8][2] * w1, ad[mt][n8][3] * w1);
            *(float2*)&g_Y[(size_t)(r0 + 8) * DHID + c] = o1;
        }
    }
}

// ---------------- L5: combine ----------------
__global__ void __launch_bounds__(256) k_combine(float* __restrict__ out) {
    int t = blockIdx.x, tid = threadIdx.x;
    int d0 = tid << 2;
    float4 acc = make_float4(0.f, 0.f, 0.f, 0.f);
#pragma unroll
    for (int k = 0; k < 9; k++) {
        int r = g_token_rows[t * 9 + k];
        float4 v = *(const float4*)&g_Y[(size_t)r * DHID + d0];
        acc.x += v.x; acc.y += v.y; acc.z += v.z; acc.w += v.w;
    }
    *(float4*)&out[(size_t)t * DHID + d0] = acc;
}

// ---------------- launch ----------------
extern "C" void kernel_launch(void* const* d_in, const int* in_sizes, int n_in,
                              void* d_out, int out_size) {
    const float* x       = (const float*)d_in[0];
    const float* gate_w  = (const float*)d_in[1];
    const float* ebias   = (const float*)d_in[2];
    const float* w_gate  = (const float*)d_in[3];
    const float* w_up    = (const float*)d_in[4];
    const float* w_down  = (const float*)d_in[5];
    const float* sh_gate = (const float*)d_in[6];
    const float* sh_up   = (const float*)d_in[7];
    const float* sh_down = (const float*)d_in[8];
    float* out = (float*)d_out;

    cudaFuncSetAttribute(k_gemm1, cudaFuncAttributeMaxDynamicSharedMemorySize, SMEM1_BYTES);
    cudaFuncSetAttribute(k_gemm2, cudaFuncAttributeMaxDynamicSharedMemorySize, SMEM2_BYTES);

    __half *xh, *xl, *wgh, *wgl, *wuh, *wul, *wdh, *wdl;
    cudaGetSymbolAddress((void**)&xh, g_xh);  cudaGetSymbolAddress((void**)&xl, g_xl);
    cudaGetSymbolAddress((void**)&wgh, g_wgh); cudaGetSymbolAddress((void**)&wgl, g_wgl);
    cudaGetSymbolAddress((void**)&wuh, g_wuh); cudaGetSymbolAddress((void**)&wul, g_wul);
    cudaGetSymbolAddress((void**)&wdh, g_wdh); cudaGetSymbolAddress((void**)&wdl, g_wdl);

    const size_t SHOFF = (size_t)16 * WSZ;
    const int BX = 1024, BW = 16384, BS = 1024;
    SplitArgs sa;
    sa.src[0] = x;       sa.hi[0] = xh;          sa.lo[0] = xl;
    sa.src[1] = w_gate;  sa.hi[1] = wgh;         sa.lo[1] = wgl;
    sa.src[2] = sh_gate; sa.hi[2] = wgh + SHOFF; sa.lo[2] = wgl + SHOFF;
    sa.src[3] = w_up;    sa.hi[3] = wuh;         sa.lo[3] = wul;
    sa.src[4] = sh_up;   sa.hi[4] = wuh + SHOFF; sa.lo[4] = wul + SHOFF;
    sa.src[5] = w_down;  sa.hi[5] = wdh;         sa.lo[5] = wdl;
    sa.src[6] = sh_down; sa.hi[6] = wdh + SHOFF; sa.lo[6] = wdl + SHOFF;
    int acc = 0;
    const int bc[7] = {BX, BW, BS, BW, BS, BW, BS};
    for (int i = 0; i < 7; i++) { acc += bc[i]; sa.blk_end[i] = acc; }
    sa.split_blocks = acc;
    int init_blocks = (ROWS_CAP + 255) / 256;

    k_split_all<<<acc + init_blocks, 256>>>(sa);                  // idx 0
    k_route<<<T_TOK, 128>>>(x, gate_w, ebias);                    // idx 1
    k_offsets_scatter<<<1, 256>>>();                              // idx 2
    k_gemm1<<<dim3(ROW_TILES, NI / 64), 512, SMEM1_BYTES>>>();    // idx 3 <- ncu
    k_gemm2<<<dim3(ROW_TILES, DHID / 128), 512, SMEM2_BYTES>>>(); // idx 4
    k_combine<<<T_TOK, 256>>>(out);                               // idx 5
}